// round 3
// baseline (speedup 1.0000x reference)
#include <cuda_runtime.h>
#include <math.h>

// Problem dims (fixed by the reference)
#define BATCH 8
#define SEQ   2048
#define FIN   1024
#define HID   512
#define SC1   256
#define SC2   128
#define MTOT  (BATCH * SEQ)   // 16384 rows

// Scratch (static device globals — no allocations allowed)
__device__ float g_h  [MTOT * HID];   // 33.5 MB
__device__ float g_sup[MTOT * HID];   // 33.5 MB
__device__ float g_z1 [MTOT * SC1];   // 16.8 MB
__device__ float g_z2 [MTOT * SC2];   //  8.4 MB

// ----------------------------------------------------------------------------
// Register-blocked SGEMM: C[M,N] = A[M,K] @ B[K,N] (+bias) (+relu)
// BM=BN=128, BK=8, TM=TN=8, 256 threads. All problem dims divide evenly.
// ----------------------------------------------------------------------------
template <int ACT, bool HASBIAS>
__global__ __launch_bounds__(256)
void sgemm_kernel(const float* __restrict__ A, const float* __restrict__ B,
                  const float* __restrict__ bias, float* __restrict__ C,
                  int M, int N, int K)
{
    constexpr int BM = 128, BN = 128, BK = 8, TM = 8, TN = 8;
    __shared__ float As[BK][BM];
    __shared__ float Bs[BK][BN];

    const int tid = threadIdx.x;
    const int bm  = blockIdx.y * BM;
    const int bn  = blockIdx.x * BN;

    const int tx = tid % (BN / TN);   // 0..15
    const int ty = tid / (BN / TN);   // 0..15

    // A tile load: 128 rows x 8 cols = 256 float4 (one per thread)
    const int a_row = tid >> 1;              // tid / (BK/4)
    const int a_col = (tid & 1) * 4;
    // B tile load: 8 rows x 128 cols = 256 float4 (one per thread)
    const int b_row = tid >> 5;              // tid / (BN/4)
    const int b_col = (tid & 31) * 4;

    const float* Aptr = A + (size_t)(bm + a_row) * K + a_col;
    const float* Bptr = B + (size_t)b_row * N + bn + b_col;

    float acc[TM][TN];
#pragma unroll
    for (int i = 0; i < TM; i++)
#pragma unroll
        for (int j = 0; j < TN; j++) acc[i][j] = 0.0f;

    for (int k0 = 0; k0 < K; k0 += BK) {
        float4 av = *reinterpret_cast<const float4*>(Aptr + k0);
        As[a_col + 0][a_row] = av.x;
        As[a_col + 1][a_row] = av.y;
        As[a_col + 2][a_row] = av.z;
        As[a_col + 3][a_row] = av.w;
        *reinterpret_cast<float4*>(&Bs[b_row][b_col]) =
            *reinterpret_cast<const float4*>(Bptr + (size_t)k0 * N);
        __syncthreads();

#pragma unroll
        for (int k = 0; k < BK; k++) {
            float ra[TM], rb[TN];
            float4 a0 = *reinterpret_cast<const float4*>(&As[k][ty * TM]);
            float4 a1 = *reinterpret_cast<const float4*>(&As[k][ty * TM + 4]);
            ra[0]=a0.x; ra[1]=a0.y; ra[2]=a0.z; ra[3]=a0.w;
            ra[4]=a1.x; ra[5]=a1.y; ra[6]=a1.z; ra[7]=a1.w;
            float4 b0 = *reinterpret_cast<const float4*>(&Bs[k][tx * TN]);
            float4 b1 = *reinterpret_cast<const float4*>(&Bs[k][tx * TN + 4]);
            rb[0]=b0.x; rb[1]=b0.y; rb[2]=b0.z; rb[3]=b0.w;
            rb[4]=b1.x; rb[5]=b1.y; rb[6]=b1.z; rb[7]=b1.w;
#pragma unroll
            for (int i = 0; i < TM; i++)
#pragma unroll
                for (int j = 0; j < TN; j++)
                    acc[i][j] = fmaf(ra[i], rb[j], acc[i][j]);
        }
        __syncthreads();
    }

    // Epilogue: bias + activation, vectorized stores
    float bv[TN];
    if (HASBIAS) {
#pragma unroll
        for (int j = 0; j < TN; j++) bv[j] = bias[bn + tx * TN + j];
    }
#pragma unroll
    for (int i = 0; i < TM; i++) {
        float* Crow = C + (size_t)(bm + ty * TM + i) * N + bn + tx * TN;
#pragma unroll
        for (int j0 = 0; j0 < TN; j0 += 4) {
            float4 v = make_float4(acc[i][j0], acc[i][j0+1], acc[i][j0+2], acc[i][j0+3]);
            if (HASBIAS) { v.x += bv[j0]; v.y += bv[j0+1]; v.z += bv[j0+2]; v.w += bv[j0+3]; }
            if (ACT == 1) {
                v.x = fmaxf(v.x, 0.f); v.y = fmaxf(v.y, 0.f);
                v.z = fmaxf(v.z, 0.f); v.w = fmaxf(v.w, 0.f);
            }
            *reinterpret_cast<float4*>(Crow + j0) = v;
        }
    }
}

// ----------------------------------------------------------------------------
// Tridiagonal normalized-adjacency stencil along sequence:
// h[b,s,:] = dinv[s] * (dinv[s-1]*sup[b,s-1,:] + dinv[s]*sup[b,s,:]
//                       + dinv[s+1]*sup[b,s+1,:]) + bias
// dinv[t] = (t==0 || t==SEQ-1) ? 1/sqrt(2) : 1/sqrt(3)
// ----------------------------------------------------------------------------
template <bool RELU>
__global__ void stencil_kernel(const float* __restrict__ sup,
                               const float* __restrict__ bias,
                               float* __restrict__ out)
{
    const int idx = blockIdx.x * blockDim.x + threadIdx.x;   // over MTOT * HID/4
    if (idx >= MTOT * (HID / 4)) return;
    const int c4  = idx % (HID / 4);
    const int row = idx / (HID / 4);
    const int s   = row % SEQ;

    const float inv2 = 0.707106781186547524f;  // 1/sqrt(2)
    const float inv3 = 0.577350269189625764f;  // 1/sqrt(3)
    const float ds   = (s == 0 || s == SEQ - 1) ? inv2 : inv3;

    const float4* base = reinterpret_cast<const float4*>(sup) + (size_t)row * (HID / 4) + c4;
    float4 cen = base[0];
    float4 a;
    a.x = ds * cen.x; a.y = ds * cen.y; a.z = ds * cen.z; a.w = ds * cen.w;

    if (s > 0) {
        float dl = (s - 1 == 0) ? inv2 : inv3;
        float4 lf = base[-(HID / 4)];
        a.x = fmaf(dl, lf.x, a.x); a.y = fmaf(dl, lf.y, a.y);
        a.z = fmaf(dl, lf.z, a.z); a.w = fmaf(dl, lf.w, a.w);
    }
    if (s < SEQ - 1) {
        float dr = (s + 1 == SEQ - 1) ? inv2 : inv3;
        float4 rt = base[(HID / 4)];
        a.x = fmaf(dr, rt.x, a.x); a.y = fmaf(dr, rt.y, a.y);
        a.z = fmaf(dr, rt.z, a.z); a.w = fmaf(dr, rt.w, a.w);
    }
    const float4 bvec = reinterpret_cast<const float4*>(bias)[c4];
    float4 o;
    o.x = fmaf(ds, a.x, bvec.x); o.y = fmaf(ds, a.y, bvec.y);
    o.z = fmaf(ds, a.z, bvec.z); o.w = fmaf(ds, a.w, bvec.w);
    if (RELU) {
        o.x = fmaxf(o.x, 0.f); o.y = fmaxf(o.y, 0.f);
        o.z = fmaxf(o.z, 0.f); o.w = fmaxf(o.w, 0.f);
    }
    reinterpret_cast<float4*>(out)[(size_t)row * (HID / 4) + c4] = o;
}

// ----------------------------------------------------------------------------
// Final head: out[row] = sigmoid(dot(z2[row,:], s3_W) + s3_b)   (K = 128)
// One warp per row, float4 loads (128 = 32 lanes * 4).
// ----------------------------------------------------------------------------
__global__ void head_kernel(const float* __restrict__ z2,
                            const float* __restrict__ w,
                            const float* __restrict__ b,
                            float* __restrict__ out)
{
    const int gtid = blockIdx.x * blockDim.x + threadIdx.x;
    const int row  = gtid >> 5;
    const int lane = gtid & 31;
    if (row >= MTOT) return;

    float4 wv = reinterpret_cast<const float4*>(w)[lane];
    float4 xv = reinterpret_cast<const float4*>(z2 + (size_t)row * SC2)[lane];
    float sum = xv.x * wv.x + xv.y * wv.y + xv.z * wv.z + xv.w * wv.w;
#pragma unroll
    for (int o = 16; o > 0; o >>= 1) sum += __shfl_xor_sync(0xFFFFFFFFu, sum, o);
    if (lane == 0) {
        float v = sum + b[0];
        out[row] = 1.0f / (1.0f + expf(-v));
    }
}

// ----------------------------------------------------------------------------
extern "C" void kernel_launch(void* const* d_in, const int* in_sizes, int n_in,
                              void* d_out, int out_size)
{
    const float* x    = (const float*)d_in[0];
    const float* Wp   = (const float*)d_in[1];
    const float* bp   = (const float*)d_in[2];
    const float* gcnW = (const float*)d_in[3];
    const float* gcnb = (const float*)d_in[4];
    const float* s1W  = (const float*)d_in[5];
    const float* s1b  = (const float*)d_in[6];
    const float* s2W  = (const float*)d_in[7];
    const float* s2b  = (const float*)d_in[8];
    const float* s3W  = (const float*)d_in[9];
    const float* s3b  = (const float*)d_in[10];
    float* out = (float*)d_out;

    float *h, *sup, *z1, *z2;
    cudaGetSymbolAddress((void**)&h,   g_h);
    cudaGetSymbolAddress((void**)&sup, g_sup);
    cudaGetSymbolAddress((void**)&z1,  g_z1);
    cudaGetSymbolAddress((void**)&z2,  g_z2);

    const dim3 blk(256);
    const int st_threads = 256;
    const int st_blocks  = (MTOT * (HID / 4) + st_threads - 1) / st_threads;

    // 1) h = x @ Wp + bp              [16384,1024]x[1024,512]
    {
        dim3 grid(HID / 128, MTOT / 128);
        sgemm_kernel<0, true><<<grid, blk>>>(x, Wp, bp, h, MTOT, HID, FIN);
    }

    // 2) 3 GCN layers: sup = h @ W; h = stencil(sup) + b (+relu for first 2)
    for (int i = 0; i < 3; i++) {
        dim3 grid(HID / 128, MTOT / 128);
        sgemm_kernel<0, false><<<grid, blk>>>(h, gcnW + (size_t)i * HID * HID,
                                              nullptr, sup, MTOT, HID, HID);
        if (i < 2)
            stencil_kernel<true ><<<st_blocks, st_threads>>>(sup, gcnb + (size_t)i * HID, h);
        else
            stencil_kernel<false><<<st_blocks, st_threads>>>(sup, gcnb + (size_t)i * HID, h);
    }

    // 3) z1 = relu(h @ s1W + s1b)     [16384,512]x[512,256]
    {
        dim3 grid(SC1 / 128, MTOT / 128);
        sgemm_kernel<1, true><<<grid, blk>>>(h, s1W, s1b, z1, MTOT, SC1, HID);
    }

    // 4) z2 = relu(z1 @ s2W + s2b)    [16384,256]x[256,128]
    {
        dim3 grid(SC2 / 128, MTOT / 128);
        sgemm_kernel<1, true><<<grid, blk>>>(z1, s2W, s2b, z2, MTOT, SC2, SC1);
    }

    // 5) out = sigmoid(z2 @ s3W + s3b)   [16384,128]x[128,1]
    {
        const int threads = 256;
        const int rows_per_block = threads / 32;
        const int blocks = (MTOT + rows_per_block - 1) / rows_per_block;
        head_kernel<<<blocks, threads>>>(z2, s3W, s3b, out);
    }
}

// round 7
// speedup vs baseline: 2.4380x; 2.4380x over previous
#include <cuda_runtime.h>
#include <cuda_bf16.h>
#include <cstdint>
#include <math.h>

// Problem dims (fixed by the reference)
#define BATCH 8
#define SEQ   2048
#define FIN   1024
#define HID   512
#define SC1   256
#define SC2   128
#define MTOT  (BATCH * SEQ)   // 16384 rows

// ============================================================================
// Scratch (__device__ globals — no allocations allowed)
// ============================================================================
__device__ float          g_sup [MTOT * HID];
__device__ float          g_z2  [MTOT * SC2];
__device__ __nv_bfloat16  g_xhi [MTOT * FIN],  g_xlo [MTOT * FIN];
__device__ __nv_bfloat16  g_a0hi[MTOT * HID],  g_a0lo[MTOT * HID];
__device__ __nv_bfloat16  g_a1hi[MTOT * SC1],  g_a1lo[MTOT * SC1];
__device__ __nv_bfloat16  g_wpThi[HID * FIN],      g_wpTlo[HID * FIN];
__device__ __nv_bfloat16  g_gwThi[3 * HID * HID],  g_gwTlo[3 * HID * HID];
__device__ __nv_bfloat16  g_s1Thi[SC1 * HID],      g_s1Tlo[SC1 * HID];
__device__ __nv_bfloat16  g_s2Thi[SC2 * SC1],      g_s2Tlo[SC2 * SC1];

// ============================================================================
// Baseline-PTX tensor-core primitives (no sm_103a-only features)
// ============================================================================
__device__ __forceinline__ uint32_t smem_u32(const void* p) {
    uint32_t a;
    asm("{ .reg .u64 t; cvta.to.shared.u64 t, %1; cvt.u32.u64 %0, t; }" : "=r"(a) : "l"(p));
    return a;
}
__device__ __forceinline__ void cpasync16(uint32_t dst, const void* src) {
    asm volatile("cp.async.cg.shared.global [%0], [%1], 16;" :: "r"(dst), "l"(src) : "memory");
}
__device__ __forceinline__ void cp_commit() {
    asm volatile("cp.async.commit_group;" ::: "memory");
}
template <int N>
__device__ __forceinline__ void cp_wait() {
    asm volatile("cp.async.wait_group %0;" :: "n"(N) : "memory");
}
__device__ __forceinline__ void ldm_x4(uint32_t* r, uint32_t addr) {
    asm volatile("ldmatrix.sync.aligned.m8n8.x4.shared.b16 {%0,%1,%2,%3}, [%4];"
        : "=r"(r[0]), "=r"(r[1]), "=r"(r[2]), "=r"(r[3]) : "r"(addr));
}
__device__ __forceinline__ void mma16816(float* c, const uint32_t* a, const uint32_t* b) {
    asm volatile(
        "mma.sync.aligned.m16n8k16.row.col.f32.bf16.bf16.f32 "
        "{%0,%1,%2,%3}, {%4,%5,%6,%7}, {%8,%9}, {%0,%1,%2,%3};"
        : "+f"(c[0]), "+f"(c[1]), "+f"(c[2]), "+f"(c[3])
        : "r"(a[0]), "r"(a[1]), "r"(a[2]), "r"(a[3]), "r"(b[0]), "r"(b[1]));
}

// SMEM tile: 128 rows x 32 bf16 (64 B/row). XOR swizzle on 16B chunks keeps
// both cp.async stores and ldmatrix loads bank-conflict-free:
//   offset = r*64 + ((c16 ^ ((r>>1)&3)) << 4),  c16 = (k_within_chunk / 8)
__device__ __forceinline__ uint32_t swz(int r, int c16) {
    return (uint32_t)(r * 64 + (((c16) ^ ((r >> 1) & 3)) << 4));
}

// ============================================================================
// bf16 split-precision GEMM: C[M,N] = (Ahi+Alo)[M,K] @ (Bhi+Blo)[N,K]^T
// 3 HMMA passes (hi*hi + hi*lo + lo*hi), fp32 accumulate.
// BM=BN=128, BK=32, 256 threads (8 warps, 4x2), warp tile 32x64.
// OUTMODE 0: fp32 C.  OUTMODE 1: bf16 hi/lo C (re-split in epilogue).
// ============================================================================
#define BM 128
#define BN 128
#define BKC 32
#define ABUF 8192            // bytes per tile buffer (128 rows * 64 B)
#define STAGE (4 * ABUF)     // Ahi, Alo, Bhi, Blo
#define GEMM_SMEM (2 * STAGE)  // 65536 B, double buffered

template <int ACT, int HASBIAS, int OUTMODE>
__global__ __launch_bounds__(256, 1)
void mma_gemm(const __nv_bfloat16* __restrict__ Ahi, const __nv_bfloat16* __restrict__ Alo,
              const __nv_bfloat16* __restrict__ Bhi, const __nv_bfloat16* __restrict__ Blo,
              const float* __restrict__ bias,
              float* __restrict__ Cf,
              __nv_bfloat16* __restrict__ Chi, __nv_bfloat16* __restrict__ Clo,
              int M, int N, int K)
{
    extern __shared__ char smem[];
    const uint32_t sb = smem_u32(smem);
    const int tid = threadIdx.x;
    const int wid = tid >> 5, lid = tid & 31;
    const int wm = wid & 3, wn = wid >> 2;          // 4 x 2 warp grid
    const int m0 = blockIdx.y * BM, n0 = blockIdx.x * BN;

    // cp.async g2s for one K-chunk into one stage
    auto g2s = [&](int c, int st) {
        const uint32_t base = sb + st * STAGE;
        const __nv_bfloat16* srcs[4] = {
            Ahi + (size_t)m0 * K + c * BKC,
            Alo + (size_t)m0 * K + c * BKC,
            Bhi + (size_t)n0 * K + c * BKC,
            Blo + (size_t)n0 * K + c * BKC };
#pragma unroll
        for (int t = 0; t < 4; t++) {
#pragma unroll
            for (int i = 0; i < 2; i++) {
                const int q = tid + i * 256;          // 0..511
                const int r = q >> 2, c16 = q & 3;
                cpasync16(base + t * ABUF + swz(r, c16),
                          srcs[t] + (size_t)r * K + c16 * 8);
            }
        }
    };

    float acc[2][8][4];
#pragma unroll
    for (int i = 0; i < 2; i++)
#pragma unroll
        for (int j = 0; j < 8; j++)
#pragma unroll
            for (int q = 0; q < 4; q++) acc[i][j][q] = 0.0f;

    // ldmatrix lane decomposition
    const int lt = lid >> 3;         // tile index 0..3 within x4
    const int lj = lid & 7;          // row within 8x8 tile

    const int NC = K / BKC;
    g2s(0, 0); cp_commit();

    for (int c = 0; c < NC; c++) {
        if (c + 1 < NC) { g2s(c + 1, (c + 1) & 1); cp_commit(); cp_wait<1>(); }
        else            { cp_wait<0>(); }
        __syncthreads();

        const uint32_t stg = sb + (c & 1) * STAGE;
        const uint32_t sAh = stg, sAl = stg + ABUF, sBh = stg + 2 * ABUF, sBl = stg + 3 * ABUF;

#pragma unroll
        for (int kk = 0; kk < BKC; kk += 16) {
            // A fragments (m16k16): x4 tiles (m0k0, m8k0, m0k8, m8k8)
            uint32_t ah[2][4], al[2][4];
#pragma unroll
            for (int mi = 0; mi < 2; mi++) {
                const int rowA = wm * 32 + mi * 16 + lj + ((lt & 1) << 3);
                const int kc16 = (kk + ((lt >> 1) << 3)) >> 3;
                ldm_x4(ah[mi], sAh + swz(rowA, kc16));
                ldm_x4(al[mi], sAl + swz(rowA, kc16));
            }
            // B fragments (two n8k16 per x4): tiles (n0k0, n0k8, n8k0, n8k8)
            uint32_t bh[4][4], bl[4][4];
#pragma unroll
            for (int nb = 0; nb < 4; nb++) {
                const int rowB = wn * 64 + nb * 16 + lj + ((lt >> 1) << 3);
                const int kc16 = (kk + ((lt & 1) << 3)) >> 3;
                ldm_x4(bh[nb], sBh + swz(rowB, kc16));
                ldm_x4(bl[nb], sBl + swz(rowB, kc16));
            }
            // 3-pass split-precision MMA
#pragma unroll
            for (int mi = 0; mi < 2; mi++)
#pragma unroll
                for (int nb = 0; nb < 4; nb++) {
                    mma16816(acc[mi][2 * nb],     ah[mi], &bh[nb][0]);
                    mma16816(acc[mi][2 * nb + 1], ah[mi], &bh[nb][2]);
                    mma16816(acc[mi][2 * nb],     ah[mi], &bl[nb][0]);
                    mma16816(acc[mi][2 * nb + 1], ah[mi], &bl[nb][2]);
                    mma16816(acc[mi][2 * nb],     al[mi], &bh[nb][0]);
                    mma16816(acc[mi][2 * nb + 1], al[mi], &bh[nb][2]);
                }
        }
        __syncthreads();
    }

    // Epilogue: C frag: c0,c1 at (row, col..col+1); c2,c3 at (row+8, ...)
    const int tq = lid >> 2, tr = lid & 3;
#pragma unroll
    for (int ni = 0; ni < 8; ni++) {
        const int col = n0 + wn * 64 + ni * 8 + tr * 2;
        float b0 = 0.f, b1 = 0.f;
        if (HASBIAS) { b0 = bias[col]; b1 = bias[col + 1]; }
#pragma unroll
        for (int mi = 0; mi < 2; mi++) {
            const int row = m0 + wm * 32 + mi * 16 + tq;
            float v0 = acc[mi][ni][0] + b0, v1 = acc[mi][ni][1] + b1;
            float v2 = acc[mi][ni][2] + b0, v3 = acc[mi][ni][3] + b1;
            if (ACT) {
                v0 = fmaxf(v0, 0.f); v1 = fmaxf(v1, 0.f);
                v2 = fmaxf(v2, 0.f); v3 = fmaxf(v3, 0.f);
            }
            if (OUTMODE == 0) {
                *reinterpret_cast<float2*>(Cf + (size_t)row * N + col)       = make_float2(v0, v1);
                *reinterpret_cast<float2*>(Cf + (size_t)(row + 8) * N + col) = make_float2(v2, v3);
            } else {
                __nv_bfloat16 h0 = __float2bfloat16(v0), h1 = __float2bfloat16(v1);
                __nv_bfloat16 h2 = __float2bfloat16(v2), h3 = __float2bfloat16(v3);
                __nv_bfloat16 l0 = __float2bfloat16(v0 - __bfloat162float(h0));
                __nv_bfloat16 l1 = __float2bfloat16(v1 - __bfloat162float(h1));
                __nv_bfloat16 l2 = __float2bfloat16(v2 - __bfloat162float(h2));
                __nv_bfloat16 l3 = __float2bfloat16(v3 - __bfloat162float(h3));
                *reinterpret_cast<uint32_t*>(Chi + (size_t)row * N + col) =
                    (uint32_t)__bfloat16_as_ushort(h0) | ((uint32_t)__bfloat16_as_ushort(h1) << 16);
                *reinterpret_cast<uint32_t*>(Clo + (size_t)row * N + col) =
                    (uint32_t)__bfloat16_as_ushort(l0) | ((uint32_t)__bfloat16_as_ushort(l1) << 16);
                *reinterpret_cast<uint32_t*>(Chi + (size_t)(row + 8) * N + col) =
                    (uint32_t)__bfloat16_as_ushort(h2) | ((uint32_t)__bfloat16_as_ushort(h3) << 16);
                *reinterpret_cast<uint32_t*>(Clo + (size_t)(row + 8) * N + col) =
                    (uint32_t)__bfloat16_as_ushort(l2) | ((uint32_t)__bfloat16_as_ushort(l3) << 16);
            }
        }
    }
}

// ============================================================================
// Elementwise converters
// ============================================================================
__device__ __forceinline__ void split1(float v, uint32_t& h, uint32_t& l) {
    __nv_bfloat16 hb = __float2bfloat16(v);
    __nv_bfloat16 lb = __float2bfloat16(v - __bfloat162float(hb));
    h = __bfloat16_as_ushort(hb); l = __bfloat16_as_ushort(lb);
}

__global__ void split_convert(const float4* __restrict__ in,
                              uint2* __restrict__ hi, uint2* __restrict__ lo, int n4)
{
    const int i = blockIdx.x * blockDim.x + threadIdx.x;
    if (i >= n4) return;
    const float4 v = in[i];
    uint32_t h0,h1,h2,h3,l0,l1,l2,l3;
    split1(v.x,h0,l0); split1(v.y,h1,l1); split1(v.z,h2,l2); split1(v.w,h3,l3);
    hi[i] = make_uint2(h0 | (h1 << 16), h2 | (h3 << 16));
    lo[i] = make_uint2(l0 | (l1 << 16), l2 | (l3 << 16));
}

// W [K,N] fp32 -> WT [N,K] bf16 hi/lo (small, once per launch)
__global__ void transpose_split(const float* __restrict__ W,
                                __nv_bfloat16* __restrict__ hi,
                                __nv_bfloat16* __restrict__ lo, int K, int N)
{
    const int idx = blockIdx.x * blockDim.x + threadIdx.x;
    if (idx >= K * N) return;
    const int k = idx / N, n = idx % N;
    const float v = W[idx];
    const __nv_bfloat16 h = __float2bfloat16(v);
    hi[(size_t)n * K + k] = h;
    lo[(size_t)n * K + k] = __float2bfloat16(v - __bfloat162float(h));
}

// ============================================================================
// Tridiagonal adjacency stencil + bias (+relu), output re-split to bf16 hi/lo
// ============================================================================
template <bool RELU>
__global__ void stencil_bf16(const float* __restrict__ sup,
                             const float* __restrict__ bias,
                             __nv_bfloat16* __restrict__ hi,
                             __nv_bfloat16* __restrict__ lo)
{
    const int idx = blockIdx.x * blockDim.x + threadIdx.x;
    if (idx >= MTOT * (HID / 4)) return;
    const int c4  = idx % (HID / 4);
    const int row = idx / (HID / 4);
    const int s   = row % SEQ;

    const float inv2 = 0.707106781186547524f;
    const float inv3 = 0.577350269189625764f;
    const float ds   = (s == 0 || s == SEQ - 1) ? inv2 : inv3;

    const float4* base = reinterpret_cast<const float4*>(sup) + (size_t)row * (HID / 4) + c4;
    float4 cen = base[0];
    float4 a = make_float4(ds * cen.x, ds * cen.y, ds * cen.z, ds * cen.w);
    if (s > 0) {
        const float dl = (s - 1 == 0) ? inv2 : inv3;
        float4 lf = base[-(HID / 4)];
        a.x = fmaf(dl, lf.x, a.x); a.y = fmaf(dl, lf.y, a.y);
        a.z = fmaf(dl, lf.z, a.z); a.w = fmaf(dl, lf.w, a.w);
    }
    if (s < SEQ - 1) {
        const float dr = (s + 1 == SEQ - 1) ? inv2 : inv3;
        float4 rt = base[(HID / 4)];
        a.x = fmaf(dr, rt.x, a.x); a.y = fmaf(dr, rt.y, a.y);
        a.z = fmaf(dr, rt.z, a.z); a.w = fmaf(dr, rt.w, a.w);
    }
    const float4 bvec = reinterpret_cast<const float4*>(bias)[c4];
    float4 o = make_float4(fmaf(ds, a.x, bvec.x), fmaf(ds, a.y, bvec.y),
                           fmaf(ds, a.z, bvec.z), fmaf(ds, a.w, bvec.w));
    if (RELU) {
        o.x = fmaxf(o.x, 0.f); o.y = fmaxf(o.y, 0.f);
        o.z = fmaxf(o.z, 0.f); o.w = fmaxf(o.w, 0.f);
    }
    uint32_t h0,h1,h2,h3,l0,l1,l2,l3;
    split1(o.x,h0,l0); split1(o.y,h1,l1); split1(o.z,h2,l2); split1(o.w,h3,l3);
    const size_t e = (size_t)row * HID + c4 * 4;
    *reinterpret_cast<uint2*>(hi + e) = make_uint2(h0 | (h1 << 16), h2 | (h3 << 16));
    *reinterpret_cast<uint2*>(lo + e) = make_uint2(l0 | (l1 << 16), l2 | (l3 << 16));
}

// ============================================================================
// Final head: sigmoid(z2 @ s3_W + b), K = 128, one warp per row
// ============================================================================
__global__ void head_kernel(const float* __restrict__ z2,
                            const float* __restrict__ w,
                            const float* __restrict__ b,
                            float* __restrict__ out)
{
    const int gtid = blockIdx.x * blockDim.x + threadIdx.x;
    const int row  = gtid >> 5;
    const int lane = gtid & 31;
    if (row >= MTOT) return;
    float4 wv = reinterpret_cast<const float4*>(w)[lane];
    float4 xv = reinterpret_cast<const float4*>(z2 + (size_t)row * SC2)[lane];
    float sum = xv.x * wv.x + xv.y * wv.y + xv.z * wv.z + xv.w * wv.w;
#pragma unroll
    for (int o = 16; o > 0; o >>= 1) sum += __shfl_xor_sync(0xFFFFFFFFu, sum, o);
    if (lane == 0) out[row] = 1.0f / (1.0f + expf(-(sum + b[0])));
}

// ============================================================================
extern "C" void kernel_launch(void* const* d_in, const int* in_sizes, int n_in,
                              void* d_out, int out_size)
{
    const float* x    = (const float*)d_in[0];
    const float* Wp   = (const float*)d_in[1];
    const float* bp   = (const float*)d_in[2];
    const float* gcnW = (const float*)d_in[3];
    const float* gcnb = (const float*)d_in[4];
    const float* s1W  = (const float*)d_in[5];
    const float* s1b  = (const float*)d_in[6];
    const float* s2W  = (const float*)d_in[7];
    const float* s2b  = (const float*)d_in[8];
    const float* s3W  = (const float*)d_in[9];
    const float* s3b  = (const float*)d_in[10];
    float* out = (float*)d_out;

    float *sup, *z2;
    __nv_bfloat16 *xhi,*xlo,*a0hi,*a0lo,*a1hi,*a1lo;
    __nv_bfloat16 *wpThi,*wpTlo,*gwThi,*gwTlo,*s1Thi,*s1Tlo,*s2Thi,*s2Tlo;
    cudaGetSymbolAddress((void**)&sup,   g_sup);
    cudaGetSymbolAddress((void**)&z2,    g_z2);
    cudaGetSymbolAddress((void**)&xhi,   g_xhi);   cudaGetSymbolAddress((void**)&xlo,   g_xlo);
    cudaGetSymbolAddress((void**)&a0hi,  g_a0hi);  cudaGetSymbolAddress((void**)&a0lo,  g_a0lo);
    cudaGetSymbolAddress((void**)&a1hi,  g_a1hi);  cudaGetSymbolAddress((void**)&a1lo,  g_a1lo);
    cudaGetSymbolAddress((void**)&wpThi, g_wpThi); cudaGetSymbolAddress((void**)&wpTlo, g_wpTlo);
    cudaGetSymbolAddress((void**)&gwThi, g_gwThi); cudaGetSymbolAddress((void**)&gwTlo, g_gwTlo);
    cudaGetSymbolAddress((void**)&s1Thi, g_s1Thi); cudaGetSymbolAddress((void**)&s1Tlo, g_s1Tlo);
    cudaGetSymbolAddress((void**)&s2Thi, g_s2Thi); cudaGetSymbolAddress((void**)&s2Tlo, g_s2Tlo);

    // Opt in to 64 KB dynamic smem for each GEMM instantiation
    cudaFuncSetAttribute(mma_gemm<0,1,1>, cudaFuncAttributeMaxDynamicSharedMemorySize, GEMM_SMEM);
    cudaFuncSetAttribute(mma_gemm<0,0,0>, cudaFuncAttributeMaxDynamicSharedMemorySize, GEMM_SMEM);
    cudaFuncSetAttribute(mma_gemm<1,1,1>, cudaFuncAttributeMaxDynamicSharedMemorySize, GEMM_SMEM);
    cudaFuncSetAttribute(mma_gemm<1,1,0>, cudaFuncAttributeMaxDynamicSharedMemorySize, GEMM_SMEM);

    // --- Weight transpose + split (cheap, per launch) ---
    {
        int n;
        n = FIN * HID;  transpose_split<<<(n+255)/256, 256>>>(Wp, wpThi, wpTlo, FIN, HID);
        for (int i = 0; i < 3; i++) {
            n = HID * HID;
            transpose_split<<<(n+255)/256, 256>>>(gcnW + (size_t)i*HID*HID,
                                                  gwThi + (size_t)i*HID*HID,
                                                  gwTlo + (size_t)i*HID*HID, HID, HID);
        }
        n = HID * SC1;  transpose_split<<<(n+255)/256, 256>>>(s1W, s1Thi, s1Tlo, HID, SC1);
        n = SC1 * SC2;  transpose_split<<<(n+255)/256, 256>>>(s2W, s2Thi, s2Tlo, SC1, SC2);
    }

    // --- x -> bf16 hi/lo ---
    {
        int n4 = MTOT * FIN / 4;
        split_convert<<<(n4+255)/256, 256>>>((const float4*)x, (uint2*)xhi, (uint2*)xlo, n4);
    }

    const int st_blocks = (MTOT * (HID / 4) + 255) / 256;

    // 1) h0 = x @ Wp + bp  -> a0 (bf16 hi/lo)
    mma_gemm<0,1,1><<<dim3(HID/BN, MTOT/BM), 256, GEMM_SMEM>>>(
        xhi, xlo, wpThi, wpTlo, bp, nullptr, a0hi, a0lo, MTOT, HID, FIN);

    // 2) 3 GCN layers: sup = h @ W (fp32), then stencil+bias(+relu) -> a0 hi/lo
    for (int i = 0; i < 3; i++) {
        mma_gemm<0,0,0><<<dim3(HID/BN, MTOT/BM), 256, GEMM_SMEM>>>(
            a0hi, a0lo, gwThi + (size_t)i*HID*HID, gwTlo + (size_t)i*HID*HID,
            nullptr, sup, nullptr, nullptr, MTOT, HID, HID);
        if (i < 2)
            stencil_bf16<true ><<<st_blocks, 256>>>(sup, gcnb + (size_t)i*HID, a0hi, a0lo);
        else
            stencil_bf16<false><<<st_blocks, 256>>>(sup, gcnb + (size_t)i*HID, a0hi, a0lo);
    }

    // 3) z1 = relu(h @ s1W + s1b) -> a1 (bf16 hi/lo)
    mma_gemm<1,1,1><<<dim3(SC1/BN, MTOT/BM), 256, GEMM_SMEM>>>(
        a0hi, a0lo, s1Thi, s1Tlo, s1b, nullptr, a1hi, a1lo, MTOT, SC1, HID);

    // 4) z2 = relu(z1 @ s2W + s2b) -> fp32
    mma_gemm<1,1,0><<<dim3(SC2/BN, MTOT/BM), 256, GEMM_SMEM>>>(
        a1hi, a1lo, s2Thi, s2Tlo, s2b, z2, nullptr, nullptr, MTOT, SC2, SC1);

    // 5) out = sigmoid(z2 @ s3W + s3b)
    {
        const int blocks = (MTOT + 7) / 8;
        head_kernel<<<blocks, 256>>>(z2, s3W, s3b, out);
    }
}

// round 11
// speedup vs baseline: 2.7880x; 1.1436x over previous
#include <cuda_runtime.h>
#include <cuda_bf16.h>
#include <cstdint>
#include <math.h>

// Problem dims (fixed by the reference)
#define BATCH 8
#define SEQ   2048
#define FIN   1024
#define HID   512
#define SC1   256
#define SC2   128
#define MTOT  (BATCH * SEQ)   // 16384 rows

// ============================================================================
// Scratch (__device__ globals — no allocations allowed)
// ============================================================================
__device__ float          g_sup [MTOT * HID];
__device__ float          g_z2  [MTOT * SC2];
__device__ __nv_bfloat16  g_xhi [MTOT * FIN],  g_xlo [MTOT * FIN];
__device__ __nv_bfloat16  g_a0hi[MTOT * HID],  g_a0lo[MTOT * HID];
__device__ __nv_bfloat16  g_a1hi[MTOT * SC1],  g_a1lo[MTOT * SC1];
__device__ __nv_bfloat16  g_wpThi[HID * FIN],      g_wpTlo[HID * FIN];
__device__ __nv_bfloat16  g_gwThi[3 * HID * HID],  g_gwTlo[3 * HID * HID];
__device__ __nv_bfloat16  g_s1Thi[SC1 * HID],      g_s1Tlo[SC1 * HID];
__device__ __nv_bfloat16  g_s2Thi[SC2 * SC1],      g_s2Tlo[SC2 * SC1];

// ============================================================================
// Baseline-PTX tensor-core primitives (no sm_103a-only features)
// ============================================================================
__device__ __forceinline__ uint32_t smem_u32(const void* p) {
    uint32_t a;
    asm("{ .reg .u64 t; cvta.to.shared.u64 t, %1; cvt.u32.u64 %0, t; }" : "=r"(a) : "l"(p));
    return a;
}
__device__ __forceinline__ void cpasync16(uint32_t dst, const void* src) {
    asm volatile("cp.async.cg.shared.global [%0], [%1], 16;" :: "r"(dst), "l"(src) : "memory");
}
__device__ __forceinline__ void cp_commit() {
    asm volatile("cp.async.commit_group;" ::: "memory");
}
template <int N>
__device__ __forceinline__ void cp_wait() {
    asm volatile("cp.async.wait_group %0;" :: "n"(N) : "memory");
}
__device__ __forceinline__ void ldm_x4(uint32_t* r, uint32_t addr) {
    asm volatile("ldmatrix.sync.aligned.m8n8.x4.shared.b16 {%0,%1,%2,%3}, [%4];"
        : "=r"(r[0]), "=r"(r[1]), "=r"(r[2]), "=r"(r[3]) : "r"(addr));
}
__device__ __forceinline__ void mma16816(float* c, const uint32_t* a, const uint32_t* b) {
    asm volatile(
        "mma.sync.aligned.m16n8k16.row.col.f32.bf16.bf16.f32 "
        "{%0,%1,%2,%3}, {%4,%5,%6,%7}, {%8,%9}, {%0,%1,%2,%3};"
        : "+f"(c[0]), "+f"(c[1]), "+f"(c[2]), "+f"(c[3])
        : "r"(a[0]), "r"(a[1]), "r"(a[2]), "r"(a[3]), "r"(b[0]), "r"(b[1]));
}

// SMEM tile: 128 rows x 32 bf16 (64 B/row). XOR swizzle on 16B chunks keeps
// both cp.async stores and ldmatrix loads bank-conflict-free.
__device__ __forceinline__ uint32_t swz(int r, int c16) {
    return (uint32_t)(r * 64 + (((c16) ^ ((r >> 1) & 3)) << 4));
}

// ============================================================================
// bf16 split-precision GEMM: C[M,N] = (Ahi+Alo)[M,K] @ (Bhi+Blo)[N,K]^T
// 3 HMMA passes (hi*hi + hi*lo + lo*hi), fp32 accumulate.
// BM=BN=128, BK=32, 256 threads (8 warps, 4x2), warp tile 32x64.
// 3-stage cp.async pipeline; epilogue staged through SMEM for coalescing.
// OUTMODE 0: fp32 C.  OUTMODE 1: bf16 hi/lo C (re-split in epilogue).
// ============================================================================
#define BM 128
#define BN 128
#define BKC 32
#define ABUF 8192              // bytes per tile buffer (128 rows * 64 B)
#define STAGE (4 * ABUF)       // Ahi, Alo, Bhi, Blo = 32 KB
#define NSTAGE 3
#define GEMM_SMEM (NSTAGE * STAGE)   // 98304 B
#define EPI_STRIDE 130         // padded fp32 row stride for epilogue staging

template <int ACT, int HASBIAS, int OUTMODE>
__global__ __launch_bounds__(256, 2)
void mma_gemm(const __nv_bfloat16* __restrict__ Ahi, const __nv_bfloat16* __restrict__ Alo,
              const __nv_bfloat16* __restrict__ Bhi, const __nv_bfloat16* __restrict__ Blo,
              const float* __restrict__ bias,
              float* __restrict__ Cf,
              __nv_bfloat16* __restrict__ Chi, __nv_bfloat16* __restrict__ Clo,
              int M, int N, int K)
{
    extern __shared__ char smem[];
    const uint32_t sb = smem_u32(smem);
    const int tid = threadIdx.x;
    const int wid = tid >> 5, lid = tid & 31;
    const int wm = wid & 3, wn = wid >> 2;          // 4 x 2 warp grid
    const int m0 = blockIdx.y * BM, n0 = blockIdx.x * BN;

    // cp.async g2s for one K-chunk into one stage
    auto g2s = [&](int c, int st) {
        const uint32_t base = sb + st * STAGE;
        const __nv_bfloat16* srcs[4] = {
            Ahi + (size_t)m0 * K + c * BKC,
            Alo + (size_t)m0 * K + c * BKC,
            Bhi + (size_t)n0 * K + c * BKC,
            Blo + (size_t)n0 * K + c * BKC };
#pragma unroll
        for (int t = 0; t < 4; t++) {
#pragma unroll
            for (int i = 0; i < 2; i++) {
                const int q = tid + i * 256;          // 0..511
                const int r = q >> 2, c16 = q & 3;
                cpasync16(base + t * ABUF + swz(r, c16),
                          srcs[t] + (size_t)r * K + c16 * 8);
            }
        }
    };

    float acc[2][8][4];
#pragma unroll
    for (int i = 0; i < 2; i++)
#pragma unroll
        for (int j = 0; j < 8; j++)
#pragma unroll
            for (int q = 0; q < 4; q++) acc[i][j][q] = 0.0f;

    // ldmatrix lane decomposition
    const int lt = lid >> 3;         // tile index 0..3 within x4
    const int lj = lid & 7;          // row within 8x8 tile

    const int NC = K / BKC;          // >= 8 for all layers
    g2s(0, 0); cp_commit();
    g2s(1, 1); cp_commit();

    for (int c = 0; c < NC; c++) {
        // wait for stage c to land (the next stage may remain in flight)
        if (c + 1 < NC) cp_wait<1>(); else cp_wait<0>();
        __syncthreads();                              // also fences stage reuse
        if (c + 2 < NC) { g2s(c + 2, (c + 2) % NSTAGE); cp_commit(); }

        const uint32_t stg = sb + (c % NSTAGE) * STAGE;
        const uint32_t sAh = stg, sAl = stg + ABUF, sBh = stg + 2 * ABUF, sBl = stg + 3 * ABUF;

#pragma unroll
        for (int kk = 0; kk < BKC; kk += 16) {
            // A fragments (m16k16): x4 tiles (m0k0, m8k0, m0k8, m8k8)
            uint32_t ah[2][4], al[2][4];
#pragma unroll
            for (int mi = 0; mi < 2; mi++) {
                const int rowA = wm * 32 + mi * 16 + lj + ((lt & 1) << 3);
                const int kc16 = (kk + ((lt >> 1) << 3)) >> 3;
                ldm_x4(ah[mi], sAh + swz(rowA, kc16));
                ldm_x4(al[mi], sAl + swz(rowA, kc16));
            }
            // B fragments (two n8k16 per x4): tiles (n0k0, n0k8, n8k0, n8k8)
            uint32_t bh[4][4], bl[4][4];
#pragma unroll
            for (int nb = 0; nb < 4; nb++) {
                const int rowB = wn * 64 + nb * 16 + lj + ((lt >> 1) << 3);
                const int kc16 = (kk + ((lt & 1) << 3)) >> 3;
                ldm_x4(bh[nb], sBh + swz(rowB, kc16));
                ldm_x4(bl[nb], sBl + swz(rowB, kc16));
            }
            // 3-pass split-precision MMA
#pragma unroll
            for (int mi = 0; mi < 2; mi++)
#pragma unroll
                for (int nb = 0; nb < 4; nb++) {
                    mma16816(acc[mi][2 * nb],     ah[mi], &bh[nb][0]);
                    mma16816(acc[mi][2 * nb + 1], ah[mi], &bh[nb][2]);
                    mma16816(acc[mi][2 * nb],     ah[mi], &bl[nb][0]);
                    mma16816(acc[mi][2 * nb + 1], ah[mi], &bl[nb][2]);
                    mma16816(acc[mi][2 * nb],     al[mi], &bh[nb][0]);
                    mma16816(acc[mi][2 * nb + 1], al[mi], &bh[nb][2]);
                }
        }
    }

    // ---------------- Epilogue (staged through SMEM for coalescing) ---------
    __syncthreads();                       // all warps done reading stages
    float* sc = reinterpret_cast<float*>(smem);
    {
        const int tq = lid >> 2, tr = lid & 3;
#pragma unroll
        for (int ni = 0; ni < 8; ni++) {
            const int col = wn * 64 + ni * 8 + tr * 2;
#pragma unroll
            for (int mi = 0; mi < 2; mi++) {
                const int row = wm * 32 + mi * 16 + tq;
                sc[row * EPI_STRIDE + col]           = acc[mi][ni][0];
                sc[row * EPI_STRIDE + col + 1]       = acc[mi][ni][1];
                sc[(row + 8) * EPI_STRIDE + col]     = acc[mi][ni][2];
                sc[(row + 8) * EPI_STRIDE + col + 1] = acc[mi][ni][3];
            }
        }
    }
    __syncthreads();

    // Each warp writes 16 rows; lane l handles 4 consecutive columns.
    {
        const int cl = lid * 4;
        float b0 = 0.f, b1 = 0.f, b2 = 0.f, b3 = 0.f;
        if (HASBIAS) {
            const float4 bv = *reinterpret_cast<const float4*>(bias + n0 + cl);
            b0 = bv.x; b1 = bv.y; b2 = bv.z; b3 = bv.w;
        }
#pragma unroll
        for (int i = 0; i < 16; i++) {
            const int r = wid * 16 + i;
            const float* sp = sc + r * EPI_STRIDE + cl;
            float v0 = sp[0] + b0, v1 = sp[1] + b1, v2 = sp[2] + b2, v3 = sp[3] + b3;
            if (ACT) {
                v0 = fmaxf(v0, 0.f); v1 = fmaxf(v1, 0.f);
                v2 = fmaxf(v2, 0.f); v3 = fmaxf(v3, 0.f);
            }
            const size_t base = (size_t)(m0 + r) * N + n0 + cl;
            if (OUTMODE == 0) {
                *reinterpret_cast<float4*>(Cf + base) = make_float4(v0, v1, v2, v3);
            } else {
                __nv_bfloat16 h0 = __float2bfloat16(v0), h1 = __float2bfloat16(v1);
                __nv_bfloat16 h2 = __float2bfloat16(v2), h3 = __float2bfloat16(v3);
                __nv_bfloat16 l0 = __float2bfloat16(v0 - __bfloat162float(h0));
                __nv_bfloat16 l1 = __float2bfloat16(v1 - __bfloat162float(h1));
                __nv_bfloat16 l2 = __float2bfloat16(v2 - __bfloat162float(h2));
                __nv_bfloat16 l3 = __float2bfloat16(v3 - __bfloat162float(h3));
                uint2 ph, pl;
                ph.x = (uint32_t)__bfloat16_as_ushort(h0) | ((uint32_t)__bfloat16_as_ushort(h1) << 16);
                ph.y = (uint32_t)__bfloat16_as_ushort(h2) | ((uint32_t)__bfloat16_as_ushort(h3) << 16);
                pl.x = (uint32_t)__bfloat16_as_ushort(l0) | ((uint32_t)__bfloat16_as_ushort(l1) << 16);
                pl.y = (uint32_t)__bfloat16_as_ushort(l2) | ((uint32_t)__bfloat16_as_ushort(l3) << 16);
                *reinterpret_cast<uint2*>(Chi + base) = ph;
                *reinterpret_cast<uint2*>(Clo + base) = pl;
            }
        }
    }
}

// ============================================================================
// Elementwise converters
// ============================================================================
__device__ __forceinline__ void split1(float v, uint32_t& h, uint32_t& l) {
    __nv_bfloat16 hb = __float2bfloat16(v);
    __nv_bfloat16 lb = __float2bfloat16(v - __bfloat162float(hb));
    h = __bfloat16_as_ushort(hb); l = __bfloat16_as_ushort(lb);
}

__global__ void split_convert(const float4* __restrict__ in,
                              uint2* __restrict__ hi, uint2* __restrict__ lo, int n4)
{
    const int i = blockIdx.x * blockDim.x + threadIdx.x;
    if (i >= n4) return;
    const float4 v = in[i];
    uint32_t h0,h1,h2,h3,l0,l1,l2,l3;
    split1(v.x,h0,l0); split1(v.y,h1,l1); split1(v.z,h2,l2); split1(v.w,h3,l3);
    hi[i] = make_uint2(h0 | (h1 << 16), h2 | (h3 << 16));
    lo[i] = make_uint2(l0 | (l1 << 16), l2 | (l3 << 16));
}

// Tiled W [K,N] fp32 -> WT [N,K] bf16 hi/lo. 32x32 tiles via smem,
// coalesced reads and packed 8B writes. Grid: (K/32, N/32), 256 threads.
__global__ void transpose_split_tiled(const float* __restrict__ W,
                                      __nv_bfloat16* __restrict__ hi,
                                      __nv_bfloat16* __restrict__ lo, int K, int N)
{
    __shared__ float tile[32][33];
    const int k0 = blockIdx.x * 32, n0 = blockIdx.y * 32;
    {
        const int c = threadIdx.x & 31, r8 = threadIdx.x >> 5;   // c: col, r8: 0..7
#pragma unroll
        for (int r = r8; r < 32; r += 8)
            tile[r][c] = W[(size_t)(k0 + r) * N + n0 + c];
    }
    __syncthreads();
    const int nloc = threadIdx.x >> 3;       // 0..31
    const int kq   = threadIdx.x & 7;        // 4 k's each
    const float f0 = tile[kq * 4 + 0][nloc];
    const float f1 = tile[kq * 4 + 1][nloc];
    const float f2 = tile[kq * 4 + 2][nloc];
    const float f3 = tile[kq * 4 + 3][nloc];
    uint32_t h0,h1,h2,h3,l0,l1,l2,l3;
    split1(f0,h0,l0); split1(f1,h1,l1); split1(f2,h2,l2); split1(f3,h3,l3);
    const size_t base = (size_t)(n0 + nloc) * K + k0 + kq * 4;
    *reinterpret_cast<uint2*>(hi + base) = make_uint2(h0 | (h1 << 16), h2 | (h3 << 16));
    *reinterpret_cast<uint2*>(lo + base) = make_uint2(l0 | (l1 << 16), l2 | (l3 << 16));
}

// ============================================================================
// Tridiagonal adjacency stencil + bias (+relu), output re-split to bf16 hi/lo
// ============================================================================
template <bool RELU>
__global__ void stencil_bf16(const float* __restrict__ sup,
                             const float* __restrict__ bias,
                             __nv_bfloat16* __restrict__ hi,
                             __nv_bfloat16* __restrict__ lo)
{
    const int idx = blockIdx.x * blockDim.x + threadIdx.x;
    if (idx >= MTOT * (HID / 4)) return;
    const int c4  = idx % (HID / 4);
    const int row = idx / (HID / 4);
    const int s   = row % SEQ;

    const float inv2 = 0.707106781186547524f;
    const float inv3 = 0.577350269189625764f;
    const float ds   = (s == 0 || s == SEQ - 1) ? inv2 : inv3;

    const float4* base = reinterpret_cast<const float4*>(sup) + (size_t)row * (HID / 4) + c4;
    float4 cen = base[0];
    float4 a = make_float4(ds * cen.x, ds * cen.y, ds * cen.z, ds * cen.w);
    if (s > 0) {
        const float dl = (s - 1 == 0) ? inv2 : inv3;
        float4 lf = base[-(HID / 4)];
        a.x = fmaf(dl, lf.x, a.x); a.y = fmaf(dl, lf.y, a.y);
        a.z = fmaf(dl, lf.z, a.z); a.w = fmaf(dl, lf.w, a.w);
    }
    if (s < SEQ - 1) {
        const float dr = (s + 1 == SEQ - 1) ? inv2 : inv3;
        float4 rt = base[(HID / 4)];
        a.x = fmaf(dr, rt.x, a.x); a.y = fmaf(dr, rt.y, a.y);
        a.z = fmaf(dr, rt.z, a.z); a.w = fmaf(dr, rt.w, a.w);
    }
    const float4 bvec = reinterpret_cast<const float4*>(bias)[c4];
    float4 o = make_float4(fmaf(ds, a.x, bvec.x), fmaf(ds, a.y, bvec.y),
                           fmaf(ds, a.z, bvec.z), fmaf(ds, a.w, bvec.w));
    if (RELU) {
        o.x = fmaxf(o.x, 0.f); o.y = fmaxf(o.y, 0.f);
        o.z = fmaxf(o.z, 0.f); o.w = fmaxf(o.w, 0.f);
    }
    uint32_t h0,h1,h2,h3,l0,l1,l2,l3;
    split1(o.x,h0,l0); split1(o.y,h1,l1); split1(o.z,h2,l2); split1(o.w,h3,l3);
    const size_t e = (size_t)row * HID + c4 * 4;
    *reinterpret_cast<uint2*>(hi + e) = make_uint2(h0 | (h1 << 16), h2 | (h3 << 16));
    *reinterpret_cast<uint2*>(lo + e) = make_uint2(l0 | (l1 << 16), l2 | (l3 << 16));
}

// ============================================================================
// Final head: sigmoid(z2 @ s3_W + b), K = 128, one warp per row
// ============================================================================
__global__ void head_kernel(const float* __restrict__ z2,
                            const float* __restrict__ w,
                            const float* __restrict__ b,
                            float* __restrict__ out)
{
    const int gtid = blockIdx.x * blockDim.x + threadIdx.x;
    const int row  = gtid >> 5;
    const int lane = gtid & 31;
    if (row >= MTOT) return;
    float4 wv = reinterpret_cast<const float4*>(w)[lane];
    float4 xv = reinterpret_cast<const float4*>(z2 + (size_t)row * SC2)[lane];
    float sum = xv.x * wv.x + xv.y * wv.y + xv.z * wv.z + xv.w * wv.w;
#pragma unroll
    for (int o = 16; o > 0; o >>= 1) sum += __shfl_xor_sync(0xFFFFFFFFu, sum, o);
    if (lane == 0) out[row] = 1.0f / (1.0f + expf(-(sum + b[0])));
}

// ============================================================================
extern "C" void kernel_launch(void* const* d_in, const int* in_sizes, int n_in,
                              void* d_out, int out_size)
{
    const float* x    = (const float*)d_in[0];
    const float* Wp   = (const float*)d_in[1];
    const float* bp   = (const float*)d_in[2];
    const float* gcnW = (const float*)d_in[3];
    const float* gcnb = (const float*)d_in[4];
    const float* s1W  = (const float*)d_in[5];
    const float* s1b  = (const float*)d_in[6];
    const float* s2W  = (const float*)d_in[7];
    const float* s2b  = (const float*)d_in[8];
    const float* s3W  = (const float*)d_in[9];
    const float* s3b  = (const float*)d_in[10];
    float* out = (float*)d_out;

    float *sup, *z2;
    __nv_bfloat16 *xhi,*xlo,*a0hi,*a0lo,*a1hi,*a1lo;
    __nv_bfloat16 *wpThi,*wpTlo,*gwThi,*gwTlo,*s1Thi,*s1Tlo,*s2Thi,*s2Tlo;
    cudaGetSymbolAddress((void**)&sup,   g_sup);
    cudaGetSymbolAddress((void**)&z2,    g_z2);
    cudaGetSymbolAddress((void**)&xhi,   g_xhi);   cudaGetSymbolAddress((void**)&xlo,   g_xlo);
    cudaGetSymbolAddress((void**)&a0hi,  g_a0hi);  cudaGetSymbolAddress((void**)&a0lo,  g_a0lo);
    cudaGetSymbolAddress((void**)&a1hi,  g_a1hi);  cudaGetSymbolAddress((void**)&a1lo,  g_a1lo);
    cudaGetSymbolAddress((void**)&wpThi, g_wpThi); cudaGetSymbolAddress((void**)&wpTlo, g_wpTlo);
    cudaGetSymbolAddress((void**)&gwThi, g_gwThi); cudaGetSymbolAddress((void**)&gwTlo, g_gwTlo);
    cudaGetSymbolAddress((void**)&s1Thi, g_s1Thi); cudaGetSymbolAddress((void**)&s1Tlo, g_s1Tlo);
    cudaGetSymbolAddress((void**)&s2Thi, g_s2Thi); cudaGetSymbolAddress((void**)&s2Tlo, g_s2Tlo);

    // Opt in to 96 KB dynamic smem for each GEMM instantiation
    cudaFuncSetAttribute(mma_gemm<0,1,1>, cudaFuncAttributeMaxDynamicSharedMemorySize, GEMM_SMEM);
    cudaFuncSetAttribute(mma_gemm<0,0,0>, cudaFuncAttributeMaxDynamicSharedMemorySize, GEMM_SMEM);
    cudaFuncSetAttribute(mma_gemm<1,1,1>, cudaFuncAttributeMaxDynamicSharedMemorySize, GEMM_SMEM);
    cudaFuncSetAttribute(mma_gemm<1,1,0>, cudaFuncAttributeMaxDynamicSharedMemorySize, GEMM_SMEM);

    // --- Weight transpose + split (tiled, cheap) ---
    transpose_split_tiled<<<dim3(FIN/32, HID/32), 256>>>(Wp, wpThi, wpTlo, FIN, HID);
    for (int i = 0; i < 3; i++)
        transpose_split_tiled<<<dim3(HID/32, HID/32), 256>>>(
            gcnW + (size_t)i*HID*HID, gwThi + (size_t)i*HID*HID,
            gwTlo + (size_t)i*HID*HID, HID, HID);
    transpose_split_tiled<<<dim3(HID/32, SC1/32), 256>>>(s1W, s1Thi, s1Tlo, HID, SC1);
    transpose_split_tiled<<<dim3(SC1/32, SC2/32), 256>>>(s2W, s2Thi, s2Tlo, SC1, SC2);

    // --- x -> bf16 hi/lo ---
    {
        int n4 = MTOT * FIN / 4;
        split_convert<<<(n4+255)/256, 256>>>((const float4*)x, (uint2*)xhi, (uint2*)xlo, n4);
    }

    const int st_blocks = (MTOT * (HID / 4) + 255) / 256;

    // 1) h0 = x @ Wp + bp  -> a0 (bf16 hi/lo)
    mma_gemm<0,1,1><<<dim3(HID/BN, MTOT/BM), 256, GEMM_SMEM>>>(
        xhi, xlo, wpThi, wpTlo, bp, nullptr, a0hi, a0lo, MTOT, HID, FIN);

    // 2) 3 GCN layers: sup = h @ W (fp32), then stencil+bias(+relu) -> a0 hi/lo
    for (int i = 0; i < 3; i++) {
        mma_gemm<0,0,0><<<dim3(HID/BN, MTOT/BM), 256, GEMM_SMEM>>>(
            a0hi, a0lo, gwThi + (size_t)i*HID*HID, gwTlo + (size_t)i*HID*HID,
            nullptr, sup, nullptr, nullptr, MTOT, HID, HID);
        if (i < 2)
            stencil_bf16<true ><<<st_blocks, 256>>>(sup, gcnb + (size_t)i*HID, a0hi, a0lo);
        else
            stencil_bf16<false><<<st_blocks, 256>>>(sup, gcnb + (size_t)i*HID, a0hi, a0lo);
    }

    // 3) z1 = relu(h @ s1W + s1b) -> a1 (bf16 hi/lo)
    mma_gemm<1,1,1><<<dim3(SC1/BN, MTOT/BM), 256, GEMM_SMEM>>>(
        a0hi, a0lo, s1Thi, s1Tlo, s1b, nullptr, a1hi, a1lo, MTOT, SC1, HID);

    // 4) z2 = relu(z1 @ s2W + s2b) -> fp32
    mma_gemm<1,1,0><<<dim3(SC2/BN, MTOT/BM), 256, GEMM_SMEM>>>(
        a1hi, a1lo, s2Thi, s2Tlo, s2b, z2, nullptr, nullptr, MTOT, SC2, SC1);

    // 5) out = sigmoid(z2 @ s3W + s3b)
    {
        const int blocks = (MTOT + 7) / 8;
        head_kernel<<<blocks, 256>>>(z2, s3W, s3b, out);
    }
}

// round 12
// speedup vs baseline: 3.6852x; 1.3218x over previous
#include <cuda_runtime.h>
#include <cuda_bf16.h>
#include <cstdint>
#include <math.h>

// Problem dims (fixed by the reference)
#define BATCH 8
#define SEQ   2048
#define FIN   1024
#define HID   512
#define SC1   256
#define SC2   128
#define MTOT  (BATCH * SEQ)   // 16384 rows

// ============================================================================
// Scratch (__device__ globals — no allocations allowed). All fp32 (tf32-rounded
// where used as MMA operands).
// ============================================================================
__device__ float g_xt [MTOT * FIN];    // x, tf32-rounded        (64 MB)
__device__ float g_a0 [MTOT * HID];    // activations, rounded   (32 MB)
__device__ float g_a1 [MTOT * SC1];    // score-layer1 act       (16 MB)
__device__ float g_sup[MTOT * HID];    // GCN support (full fp32)
__device__ float g_z2 [MTOT * SC2];
__device__ float g_wpT[HID * FIN];     // transposed+rounded weights
__device__ float g_gwT[3 * HID * HID];
__device__ float g_s1T[SC1 * HID];
__device__ float g_s2T[SC2 * SC1];

// ============================================================================
// Baseline-PTX primitives (no sm_103a-only features)
// ============================================================================
__device__ __forceinline__ uint32_t smem_u32(const void* p) {
    uint32_t a;
    asm("{ .reg .u64 t; cvta.to.shared.u64 t, %1; cvt.u32.u64 %0, t; }" : "=r"(a) : "l"(p));
    return a;
}
__device__ __forceinline__ void cpasync16(uint32_t dst, const void* src) {
    asm volatile("cp.async.cg.shared.global [%0], [%1], 16;" :: "r"(dst), "l"(src) : "memory");
}
__device__ __forceinline__ void cp_commit() {
    asm volatile("cp.async.commit_group;" ::: "memory");
}
template <int N>
__device__ __forceinline__ void cp_wait() {
    asm volatile("cp.async.wait_group %0;" :: "n"(N) : "memory");
}
__device__ __forceinline__ void ldm_x4(uint32_t* r, uint32_t addr) {
    asm volatile("ldmatrix.sync.aligned.m8n8.x4.shared.b16 {%0,%1,%2,%3}, [%4];"
        : "=r"(r[0]), "=r"(r[1]), "=r"(r[2]), "=r"(r[3]) : "r"(addr));
}
// m16n8k8 tf32 MMA, fp32 accumulate
__device__ __forceinline__ void mma16808(float* c, const uint32_t* a, const uint32_t* b) {
    asm volatile(
        "mma.sync.aligned.m16n8k8.row.col.f32.tf32.tf32.f32 "
        "{%0,%1,%2,%3}, {%4,%5,%6,%7}, {%8,%9}, {%0,%1,%2,%3};"
        : "+f"(c[0]), "+f"(c[1]), "+f"(c[2]), "+f"(c[3])
        : "r"(a[0]), "r"(a[1]), "r"(a[2]), "r"(a[3]), "r"(b[0]), "r"(b[1]));
}
// Round-to-nearest tf32 (RNA) — kills truncation bias
__device__ __forceinline__ float tf32r(float v) {
    uint32_t u; asm("cvt.rna.tf32.f32 %0, %1;" : "=r"(u) : "f"(v));
    return __uint_as_float(u);
}

// SMEM tile: 128 rows x 32 fp32 (128 B/row). XOR swizzle on 16B chunks keeps
// cp.async stores and ldmatrix loads bank-conflict-free:
//   offset = r*128 + ((c16 ^ (r & 7)) << 4)
__device__ __forceinline__ uint32_t swz32(int r, int c16) {
    return (uint32_t)(r * 128 + (((c16) ^ (r & 7)) << 4));
}

// ============================================================================
// tf32 GEMM: C[M,N] = A[M,K] @ B[N,K]^T, single pass, fp32 accumulate.
// BM=BN=128, BK=32, 256 threads (8 warps, 4x2), warp tile 32x64.
// 3-stage cp.async pipeline; epilogue staged through SMEM for coalescing.
// OUTMODE 0: plain fp32 C.  OUTMODE 1: tf32-rounded fp32 C (next GEMM operand).
// ============================================================================
#define BM 128
#define BN 128
#define BKC 32
#define TBUF (128 * 128)       // bytes per fp32 tile (128 rows * 128 B)
#define STAGE (2 * TBUF)       // A + B = 32 KB
#define NSTAGE 3
#define GEMM_SMEM (NSTAGE * STAGE)   // 98304 B
#define EPI_STRIDE 130         // padded fp32 row stride for epilogue staging

template <int ACT, int HASBIAS, int OUTMODE>
__global__ __launch_bounds__(256, 2)
void mma_gemm(const float* __restrict__ At, const float* __restrict__ Bt,
              const float* __restrict__ bias, float* __restrict__ Cf,
              int M, int N, int K)
{
    extern __shared__ char smem[];
    const uint32_t sb = smem_u32(smem);
    const int tid = threadIdx.x;
    const int wid = tid >> 5, lid = tid & 31;
    const int wm = wid & 3, wn = wid >> 2;          // 4 x 2 warp grid
    const int m0 = blockIdx.y * BM, n0 = blockIdx.x * BN;

    // cp.async g2s for one K-chunk into one stage (A tile + B tile)
    auto g2s = [&](int c, int st) {
        const uint32_t base = sb + st * STAGE;
        const float* srcA = At + (size_t)m0 * K + c * BKC;
        const float* srcB = Bt + (size_t)n0 * K + c * BKC;
#pragma unroll
        for (int i = 0; i < 4; i++) {
            const int q = tid + i * 256;              // 0..1023
            const int r = q >> 3, c16 = q & 7;
            const uint32_t so = swz32(r, c16);
            cpasync16(base + so,        srcA + (size_t)r * K + c16 * 4);
            cpasync16(base + TBUF + so, srcB + (size_t)r * K + c16 * 4);
        }
    };

    float acc[2][8][4];
#pragma unroll
    for (int i = 0; i < 2; i++)
#pragma unroll
        for (int j = 0; j < 8; j++)
#pragma unroll
            for (int q = 0; q < 4; q++) acc[i][j][q] = 0.0f;

    // ldmatrix lane decomposition
    const int lt = lid >> 3;         // tile index 0..3 within x4
    const int lj = lid & 7;          // row within 8-row tile

    const int NC = K / BKC;          // >= 8 for all layers
    g2s(0, 0); cp_commit();
    g2s(1, 1); cp_commit();

    for (int c = 0; c < NC; c++) {
        if (c + 1 < NC) cp_wait<1>(); else cp_wait<0>();
        __syncthreads();                              // also fences stage reuse
        if (c + 2 < NC) { g2s(c + 2, (c + 2) % NSTAGE); cp_commit(); }

        const uint32_t stg = sb + (c % NSTAGE) * STAGE;
        const uint32_t sA = stg, sB = stg + TBUF;

#pragma unroll
        for (int k8 = 0; k8 < 4; k8++) {              // 4 k8-steps per chunk
            const int c0 = k8 * 2;                    // c16 units (8 fp32 = 2*16B)
            // A fragments (m16k8): x4 tiles (m0,c0) (m8,c0) (m0,c0+1) (m8,c0+1)
            uint32_t a[2][4];
#pragma unroll
            for (int mi = 0; mi < 2; mi++) {
                const int rowA = wm * 32 + mi * 16 + lj + ((lt & 1) << 3);
                ldm_x4(a[mi], sA + swz32(rowA, c0 + (lt >> 1)));
            }
            // B fragments: per n16 pair, x4 tiles (n0,c0) (n0,c0+1) (n8,c0) (n8,c0+1)
            // -> r0,r1 = {b0,b1} of n8#0 ; r2,r3 = {b0,b1} of n8#1
            uint32_t bf[4][4];
#pragma unroll
            for (int np = 0; np < 4; np++) {
                const int rowB = wn * 64 + np * 16 + lj + ((lt >> 1) << 3);
                ldm_x4(bf[np], sB + swz32(rowB, c0 + (lt & 1)));
            }
#pragma unroll
            for (int mi = 0; mi < 2; mi++)
#pragma unroll
                for (int np = 0; np < 4; np++) {
                    mma16808(acc[mi][2 * np],     a[mi], &bf[np][0]);
                    mma16808(acc[mi][2 * np + 1], a[mi], &bf[np][2]);
                }
        }
    }

    // ---------------- Epilogue (staged through SMEM for coalescing) ---------
    __syncthreads();                       // all warps done reading stages
    float* sc = reinterpret_cast<float*>(smem);
    {
        const int tq = lid >> 2, tr = lid & 3;
#pragma unroll
        for (int ni = 0; ni < 8; ni++) {
            const int col = wn * 64 + ni * 8 + tr * 2;
#pragma unroll
            for (int mi = 0; mi < 2; mi++) {
                const int row = wm * 32 + mi * 16 + tq;
                sc[row * EPI_STRIDE + col]           = acc[mi][ni][0];
                sc[row * EPI_STRIDE + col + 1]       = acc[mi][ni][1];
                sc[(row + 8) * EPI_STRIDE + col]     = acc[mi][ni][2];
                sc[(row + 8) * EPI_STRIDE + col + 1] = acc[mi][ni][3];
            }
        }
    }
    __syncthreads();

    // Each warp writes 16 rows; lane l handles 4 consecutive columns.
    {
        const int cl = lid * 4;
        float b0 = 0.f, b1 = 0.f, b2 = 0.f, b3 = 0.f;
        if (HASBIAS) {
            const float4 bv = *reinterpret_cast<const float4*>(bias + n0 + cl);
            b0 = bv.x; b1 = bv.y; b2 = bv.z; b3 = bv.w;
        }
#pragma unroll
        for (int i = 0; i < 16; i++) {
            const int r = wid * 16 + i;
            const float* sp = sc + r * EPI_STRIDE + cl;
            float v0 = sp[0] + b0, v1 = sp[1] + b1, v2 = sp[2] + b2, v3 = sp[3] + b3;
            if (ACT) {
                v0 = fmaxf(v0, 0.f); v1 = fmaxf(v1, 0.f);
                v2 = fmaxf(v2, 0.f); v3 = fmaxf(v3, 0.f);
            }
            if (OUTMODE == 1) {           // feeds the next GEMM: quantize to tf32
                v0 = tf32r(v0); v1 = tf32r(v1); v2 = tf32r(v2); v3 = tf32r(v3);
            }
            *reinterpret_cast<float4*>(Cf + (size_t)(m0 + r) * N + n0 + cl) =
                make_float4(v0, v1, v2, v3);
        }
    }
}

// ============================================================================
// Elementwise converters
// ============================================================================
// x: fp32 -> tf32-rounded fp32 copy
__global__ void round_convert(const float4* __restrict__ in,
                              float4* __restrict__ outp, int n4)
{
    const int i = blockIdx.x * blockDim.x + threadIdx.x;
    if (i >= n4) return;
    const float4 v = in[i];
    outp[i] = make_float4(tf32r(v.x), tf32r(v.y), tf32r(v.z), tf32r(v.w));
}

// Tiled W [K,N] fp32 -> WT [N,K] tf32-rounded fp32. 32x32 tiles via smem.
__global__ void transpose_round_tiled(const float* __restrict__ W,
                                      float* __restrict__ WT, int K, int N)
{
    __shared__ float tile[32][33];
    const int k0 = blockIdx.x * 32, n0 = blockIdx.y * 32;
    {
        const int c = threadIdx.x & 31, r8 = threadIdx.x >> 5;
#pragma unroll
        for (int r = r8; r < 32; r += 8)
            tile[r][c] = W[(size_t)(k0 + r) * N + n0 + c];
    }
    __syncthreads();
    const int nloc = threadIdx.x >> 3;       // 0..31
    const int kq   = threadIdx.x & 7;        // 4 k's each
    const float4 o = make_float4(tf32r(tile[kq * 4 + 0][nloc]),
                                 tf32r(tile[kq * 4 + 1][nloc]),
                                 tf32r(tile[kq * 4 + 2][nloc]),
                                 tf32r(tile[kq * 4 + 3][nloc]));
    *reinterpret_cast<float4*>(WT + (size_t)(n0 + nloc) * K + k0 + kq * 4) = o;
}

// ============================================================================
// Tridiagonal adjacency stencil + bias (+relu), output tf32-rounded fp32
// ============================================================================
template <bool RELU>
__global__ void stencil_tf32(const float* __restrict__ sup,
                             const float* __restrict__ bias,
                             float* __restrict__ outp)
{
    const int idx = blockIdx.x * blockDim.x + threadIdx.x;
    if (idx >= MTOT * (HID / 4)) return;
    const int c4  = idx % (HID / 4);
    const int row = idx / (HID / 4);
    const int s   = row % SEQ;

    const float inv2 = 0.707106781186547524f;
    const float inv3 = 0.577350269189625764f;
    const float ds   = (s == 0 || s == SEQ - 1) ? inv2 : inv3;

    const float4* base = reinterpret_cast<const float4*>(sup) + (size_t)row * (HID / 4) + c4;
    float4 cen = base[0];
    float4 a = make_float4(ds * cen.x, ds * cen.y, ds * cen.z, ds * cen.w);
    if (s > 0) {
        const float dl = (s - 1 == 0) ? inv2 : inv3;
        float4 lf = base[-(HID / 4)];
        a.x = fmaf(dl, lf.x, a.x); a.y = fmaf(dl, lf.y, a.y);
        a.z = fmaf(dl, lf.z, a.z); a.w = fmaf(dl, lf.w, a.w);
    }
    if (s < SEQ - 1) {
        const float dr = (s + 1 == SEQ - 1) ? inv2 : inv3;
        float4 rt = base[(HID / 4)];
        a.x = fmaf(dr, rt.x, a.x); a.y = fmaf(dr, rt.y, a.y);
        a.z = fmaf(dr, rt.z, a.z); a.w = fmaf(dr, rt.w, a.w);
    }
    const float4 bvec = reinterpret_cast<const float4*>(bias)[c4];
    float4 o = make_float4(fmaf(ds, a.x, bvec.x), fmaf(ds, a.y, bvec.y),
                           fmaf(ds, a.z, bvec.z), fmaf(ds, a.w, bvec.w));
    if (RELU) {
        o.x = fmaxf(o.x, 0.f); o.y = fmaxf(o.y, 0.f);
        o.z = fmaxf(o.z, 0.f); o.w = fmaxf(o.w, 0.f);
    }
    // quantize for next GEMM
    o = make_float4(tf32r(o.x), tf32r(o.y), tf32r(o.z), tf32r(o.w));
    reinterpret_cast<float4*>(outp)[(size_t)row * (HID / 4) + c4] = o;
}

// ============================================================================
// Final head: sigmoid(z2 @ s3_W + b), K = 128, one warp per row
// ============================================================================
__global__ void head_kernel(const float* __restrict__ z2,
                            const float* __restrict__ w,
                            const float* __restrict__ b,
                            float* __restrict__ out)
{
    const int gtid = blockIdx.x * blockDim.x + threadIdx.x;
    const int row  = gtid >> 5;
    const int lane = gtid & 31;
    if (row >= MTOT) return;
    float4 wv = reinterpret_cast<const float4*>(w)[lane];
    float4 xv = reinterpret_cast<const float4*>(z2 + (size_t)row * SC2)[lane];
    float sum = xv.x * wv.x + xv.y * wv.y + xv.z * wv.z + xv.w * wv.w;
#pragma unroll
    for (int o = 16; o > 0; o >>= 1) sum += __shfl_xor_sync(0xFFFFFFFFu, sum, o);
    if (lane == 0) out[row] = 1.0f / (1.0f + expf(-(sum + b[0])));
}

// ============================================================================
extern "C" void kernel_launch(void* const* d_in, const int* in_sizes, int n_in,
                              void* d_out, int out_size)
{
    const float* x    = (const float*)d_in[0];
    const float* Wp   = (const float*)d_in[1];
    const float* bp   = (const float*)d_in[2];
    const float* gcnW = (const float*)d_in[3];
    const float* gcnb = (const float*)d_in[4];
    const float* s1W  = (const float*)d_in[5];
    const float* s1b  = (const float*)d_in[6];
    const float* s2W  = (const float*)d_in[7];
    const float* s2b  = (const float*)d_in[8];
    const float* s3W  = (const float*)d_in[9];
    const float* s3b  = (const float*)d_in[10];
    float* out = (float*)d_out;

    float *xt, *a0, *a1, *sup, *z2, *wpT, *gwT, *s1T, *s2T;
    cudaGetSymbolAddress((void**)&xt,  g_xt);
    cudaGetSymbolAddress((void**)&a0,  g_a0);
    cudaGetSymbolAddress((void**)&a1,  g_a1);
    cudaGetSymbolAddress((void**)&sup, g_sup);
    cudaGetSymbolAddress((void**)&z2,  g_z2);
    cudaGetSymbolAddress((void**)&wpT, g_wpT);
    cudaGetSymbolAddress((void**)&gwT, g_gwT);
    cudaGetSymbolAddress((void**)&s1T, g_s1T);
    cudaGetSymbolAddress((void**)&s2T, g_s2T);

    // Opt in to 96 KB dynamic smem for each GEMM instantiation
    cudaFuncSetAttribute(mma_gemm<0,1,1>, cudaFuncAttributeMaxDynamicSharedMemorySize, GEMM_SMEM);
    cudaFuncSetAttribute(mma_gemm<0,0,0>, cudaFuncAttributeMaxDynamicSharedMemorySize, GEMM_SMEM);
    cudaFuncSetAttribute(mma_gemm<1,1,1>, cudaFuncAttributeMaxDynamicSharedMemorySize, GEMM_SMEM);
    cudaFuncSetAttribute(mma_gemm<1,1,0>, cudaFuncAttributeMaxDynamicSharedMemorySize, GEMM_SMEM);

    // --- Weight transpose + tf32 rounding ---
    transpose_round_tiled<<<dim3(FIN/32, HID/32), 256>>>(Wp, wpT, FIN, HID);
    for (int i = 0; i < 3; i++)
        transpose_round_tiled<<<dim3(HID/32, HID/32), 256>>>(
            gcnW + (size_t)i*HID*HID, gwT + (size_t)i*HID*HID, HID, HID);
    transpose_round_tiled<<<dim3(HID/32, SC1/32), 256>>>(s1W, s1T, HID, SC1);
    transpose_round_tiled<<<dim3(SC1/32, SC2/32), 256>>>(s2W, s2T, SC1, SC2);

    // --- x -> tf32-rounded fp32 ---
    {
        int n4 = MTOT * FIN / 4;
        round_convert<<<(n4+255)/256, 256>>>((const float4*)x, (float4*)xt, n4);
    }

    const int st_blocks = (MTOT * (HID / 4) + 255) / 256;

    // 1) h0 = x @ Wp + bp  -> a0 (tf32-rounded)
    mma_gemm<0,1,1><<<dim3(HID/BN, MTOT/BM), 256, GEMM_SMEM>>>(
        xt, wpT, bp, a0, MTOT, HID, FIN);

    // 2) 3 GCN layers: sup = h @ W (fp32), then stencil+bias(+relu) -> a0
    for (int i = 0; i < 3; i++) {
        mma_gemm<0,0,0><<<dim3(HID/BN, MTOT/BM), 256, GEMM_SMEM>>>(
            a0, gwT + (size_t)i*HID*HID, nullptr, sup, MTOT, HID, HID);
        if (i < 2)
            stencil_tf32<true ><<<st_blocks, 256>>>(sup, gcnb + (size_t)i*HID, a0);
        else
            stencil_tf32<false><<<st_blocks, 256>>>(sup, gcnb + (size_t)i*HID, a0);
    }

    // 3) z1 = relu(h @ s1W + s1b) -> a1 (tf32-rounded)
    mma_gemm<1,1,1><<<dim3(SC1/BN, MTOT/BM), 256, GEMM_SMEM>>>(
        a0, s1T, s1b, a1, MTOT, SC1, HID);

    // 4) z2 = relu(z1 @ s2W + s2b) -> fp32
    mma_gemm<1,1,0><<<dim3(SC2/BN, MTOT/BM), 256, GEMM_SMEM>>>(
        a1, s2T, s2b, z2, MTOT, SC2, SC1);

    // 5) out = sigmoid(z2 @ s3W + s3b)
    {
        const int blocks = (MTOT + 7) / 8;
        head_kernel<<<blocks, 256>>>(z2, s3W, s3b, out);
    }
}

// round 13
// speedup vs baseline: 5.5547x; 1.5073x over previous
#include <cuda_runtime.h>
#include <cuda_fp16.h>
#include <cstdint>
#include <math.h>

// Problem dims (fixed by the reference)
#define BATCH 8
#define SEQ   2048
#define FIN   1024
#define HID   512
#define SC1   256
#define SC2   128
#define MTOT  (BATCH * SEQ)   // 16384 rows

// ============================================================================
// Scratch (__device__ globals — no allocations allowed)
// ============================================================================
__device__ __half g_xh [MTOT * FIN];    // x in fp16              (32 MB)
__device__ __half g_a0h[MTOT * HID];    // activations fp16       (16 MB)
__device__ __half g_a1h[MTOT * SC1];    // score-layer1 act fp16
__device__ float  g_sup[MTOT * HID];    // GCN support (full fp32)
__device__ float  g_z2 [MTOT * SC2];
__device__ __half g_wpT[HID * FIN];     // transposed fp16 weights
__device__ __half g_gwT[3 * HID * HID];
__device__ __half g_s1T[SC1 * HID];
__device__ __half g_s2T[SC2 * SC1];

// ============================================================================
// Baseline-PTX primitives (no sm_103a-only features)
// ============================================================================
__device__ __forceinline__ uint32_t smem_u32(const void* p) {
    uint32_t a;
    asm("{ .reg .u64 t; cvta.to.shared.u64 t, %1; cvt.u32.u64 %0, t; }" : "=r"(a) : "l"(p));
    return a;
}
__device__ __forceinline__ void cpasync16(uint32_t dst, const void* src) {
    asm volatile("cp.async.cg.shared.global [%0], [%1], 16;" :: "r"(dst), "l"(src) : "memory");
}
__device__ __forceinline__ void cp_commit() {
    asm volatile("cp.async.commit_group;" ::: "memory");
}
template <int N>
__device__ __forceinline__ void cp_wait() {
    asm volatile("cp.async.wait_group %0;" :: "n"(N) : "memory");
}
__device__ __forceinline__ void ldm_x4(uint32_t* r, uint32_t addr) {
    asm volatile("ldmatrix.sync.aligned.m8n8.x4.shared.b16 {%0,%1,%2,%3}, [%4];"
        : "=r"(r[0]), "=r"(r[1]), "=r"(r[2]), "=r"(r[3]) : "r"(addr));
}
// m16n8k16 fp16 MMA, fp32 accumulate
__device__ __forceinline__ void mma16816(float* c, const uint32_t* a, const uint32_t* b) {
    asm volatile(
        "mma.sync.aligned.m16n8k16.row.col.f32.f16.f16.f32 "
        "{%0,%1,%2,%3}, {%4,%5,%6,%7}, {%8,%9}, {%0,%1,%2,%3};"
        : "+f"(c[0]), "+f"(c[1]), "+f"(c[2]), "+f"(c[3])
        : "r"(a[0]), "r"(a[1]), "r"(a[2]), "r"(a[3]), "r"(b[0]), "r"(b[1]));
}

// SMEM tile: 128 rows x 32 fp16 (64 B/row). XOR swizzle on 16B chunks keeps
// both cp.async stores and ldmatrix loads bank-conflict-free.
__device__ __forceinline__ uint32_t swz(int r, int c16) {
    return (uint32_t)(r * 64 + (((c16) ^ ((r >> 1) & 3)) << 4));
}

// ============================================================================
// fp16 single-pass GEMM: C[M,N] = A[M,K] @ B[N,K]^T, fp32 accumulate.
// BM=BN=128, BK=32, 256 threads (8 warps, 4x2), warp tile 32x64.
// 4-stage cp.async pipeline (prefetch distance 3, always-commit pattern);
// epilogue staged through SMEM for coalesced writes.
// OUTMODE 0: fp32 C.  OUTMODE 1: fp16 C (next GEMM operand).
// ============================================================================
#define BM 128
#define BN 128
#define BKC 32
#define ABUF 8192              // bytes per fp16 tile (128 rows * 64 B)
#define STAGE (2 * ABUF)       // A + B = 16 KB
#define NSTAGE 4
#define GEMM_SMEM 66560        // max(NSTAGE*STAGE=65536, epi 128*130*4=66560)
#define EPI_STRIDE 130         // padded fp32 row stride for epilogue staging

template <int ACT, int HASBIAS, int OUTMODE>
__global__ __launch_bounds__(256, 2)
void mma_gemm(const __half* __restrict__ A, const __half* __restrict__ B,
              const float* __restrict__ bias,
              float* __restrict__ Cf, __half* __restrict__ Ch,
              int M, int N, int K)
{
    extern __shared__ char smem[];
    const uint32_t sb = smem_u32(smem);
    const int tid = threadIdx.x;
    const int wid = tid >> 5, lid = tid & 31;
    const int wm = wid & 3, wn = wid >> 2;          // 4 x 2 warp grid
    const int m0 = blockIdx.y * BM, n0 = blockIdx.x * BN;

    // cp.async g2s for one K-chunk into one stage (A tile + B tile)
    auto g2s = [&](int c, int st) {
        const uint32_t base = sb + st * STAGE;
        const __half* srcA = A + (size_t)m0 * K + c * BKC;
        const __half* srcB = B + (size_t)n0 * K + c * BKC;
#pragma unroll
        for (int i = 0; i < 2; i++) {
            const int q = tid + i * 256;              // 0..511
            const int r = q >> 2, c16 = q & 3;
            const uint32_t so = swz(r, c16);
            cpasync16(base + so,        srcA + (size_t)r * K + c16 * 8);
            cpasync16(base + ABUF + so, srcB + (size_t)r * K + c16 * 8);
        }
    };

    float acc[2][8][4];
#pragma unroll
    for (int i = 0; i < 2; i++)
#pragma unroll
        for (int j = 0; j < 8; j++)
#pragma unroll
            for (int q = 0; q < 4; q++) acc[i][j][q] = 0.0f;

    // ldmatrix lane decomposition
    const int lt = lid >> 3;         // tile index 0..3 within x4
    const int lj = lid & 7;          // row within 8x8 tile

    const int NC = K / BKC;          // >= 4 for all layers
    g2s(0, 0); cp_commit();
    if (NC > 1) g2s(1, 1); cp_commit();     // commit even if empty
    if (NC > 2) g2s(2, 2); cp_commit();

    for (int c = 0; c < NC; c++) {
        cp_wait<2>();                 // stage c landed (3 groups max in flight)
        __syncthreads();              // all warps see it; prior stage reads done
        if (c + 3 < NC) g2s(c + 3, (c + 3) % NSTAGE);
        cp_commit();                  // always commit to keep group count fixed

        const uint32_t stg = sb + (c % NSTAGE) * STAGE;
        const uint32_t sA = stg, sB = stg + ABUF;

#pragma unroll
        for (int kk = 0; kk < BKC; kk += 16) {
            // A fragments (m16k16): x4 tiles (m0k0, m8k0, m0k8, m8k8)
            uint32_t a[2][4];
#pragma unroll
            for (int mi = 0; mi < 2; mi++) {
                const int rowA = wm * 32 + mi * 16 + lj + ((lt & 1) << 3);
                const int kc16 = (kk + ((lt >> 1) << 3)) >> 3;
                ldm_x4(a[mi], sA + swz(rowA, kc16));
            }
            // B fragments (two n8k16 per x4): tiles (n0k0, n0k8, n8k0, n8k8)
            uint32_t bf[4][4];
#pragma unroll
            for (int nb = 0; nb < 4; nb++) {
                const int rowB = wn * 64 + nb * 16 + lj + ((lt >> 1) << 3);
                const int kc16 = (kk + ((lt & 1) << 3)) >> 3;
                ldm_x4(bf[nb], sB + swz(rowB, kc16));
            }
            // single-pass fp16 MMA
#pragma unroll
            for (int mi = 0; mi < 2; mi++)
#pragma unroll
                for (int nb = 0; nb < 4; nb++) {
                    mma16816(acc[mi][2 * nb],     a[mi], &bf[nb][0]);
                    mma16816(acc[mi][2 * nb + 1], a[mi], &bf[nb][2]);
                }
        }
    }

    // ---------------- Epilogue (staged through SMEM for coalescing) ---------
    __syncthreads();                       // all warps done reading stages
    float* sc = reinterpret_cast<float*>(smem);
    {
        const int tq = lid >> 2, tr = lid & 3;
#pragma unroll
        for (int ni = 0; ni < 8; ni++) {
            const int col = wn * 64 + ni * 8 + tr * 2;
#pragma unroll
            for (int mi = 0; mi < 2; mi++) {
                const int row = wm * 32 + mi * 16 + tq;
                sc[row * EPI_STRIDE + col]           = acc[mi][ni][0];
                sc[row * EPI_STRIDE + col + 1]       = acc[mi][ni][1];
                sc[(row + 8) * EPI_STRIDE + col]     = acc[mi][ni][2];
                sc[(row + 8) * EPI_STRIDE + col + 1] = acc[mi][ni][3];
            }
        }
    }
    __syncthreads();

    // Each warp writes 16 rows; lane l handles 4 consecutive columns.
    {
        const int cl = lid * 4;
        float b0 = 0.f, b1 = 0.f, b2 = 0.f, b3 = 0.f;
        if (HASBIAS) {
            const float4 bv = *reinterpret_cast<const float4*>(bias + n0 + cl);
            b0 = bv.x; b1 = bv.y; b2 = bv.z; b3 = bv.w;
        }
#pragma unroll
        for (int i = 0; i < 16; i++) {
            const int r = wid * 16 + i;
            const float* sp = sc + r * EPI_STRIDE + cl;
            float v0 = sp[0] + b0, v1 = sp[1] + b1, v2 = sp[2] + b2, v3 = sp[3] + b3;
            if (ACT) {
                v0 = fmaxf(v0, 0.f); v1 = fmaxf(v1, 0.f);
                v2 = fmaxf(v2, 0.f); v3 = fmaxf(v3, 0.f);
            }
            const size_t base = (size_t)(m0 + r) * N + n0 + cl;
            if (OUTMODE == 0) {
                *reinterpret_cast<float4*>(Cf + base) = make_float4(v0, v1, v2, v3);
            } else {
                const uint32_t p0 = (uint32_t)__half_as_ushort(__float2half_rn(v0))
                                  | ((uint32_t)__half_as_ushort(__float2half_rn(v1)) << 16);
                const uint32_t p1 = (uint32_t)__half_as_ushort(__float2half_rn(v2))
                                  | ((uint32_t)__half_as_ushort(__float2half_rn(v3)) << 16);
                *reinterpret_cast<uint2*>(Ch + base) = make_uint2(p0, p1);
            }
        }
    }
}

// ============================================================================
// Elementwise converters
// ============================================================================
// x: fp32 -> fp16
__global__ void half_convert(const float4* __restrict__ in,
                             uint2* __restrict__ outp, int n4)
{
    const int i = blockIdx.x * blockDim.x + threadIdx.x;
    if (i >= n4) return;
    const float4 v = in[i];
    const uint32_t p0 = (uint32_t)__half_as_ushort(__float2half_rn(v.x))
                      | ((uint32_t)__half_as_ushort(__float2half_rn(v.y)) << 16);
    const uint32_t p1 = (uint32_t)__half_as_ushort(__float2half_rn(v.z))
                      | ((uint32_t)__half_as_ushort(__float2half_rn(v.w)) << 16);
    outp[i] = make_uint2(p0, p1);
}

// Tiled W [K,N] fp32 -> WT [N,K] fp16. 32x32 tiles via smem.
__global__ void transpose_half_tiled(const float* __restrict__ W,
                                     __half* __restrict__ WT, int K, int N)
{
    __shared__ float tile[32][33];
    const int k0 = blockIdx.x * 32, n0 = blockIdx.y * 32;
    {
        const int c = threadIdx.x & 31, r8 = threadIdx.x >> 5;
#pragma unroll
        for (int r = r8; r < 32; r += 8)
            tile[r][c] = W[(size_t)(k0 + r) * N + n0 + c];
    }
    __syncthreads();
    const int nloc = threadIdx.x >> 3;       // 0..31
    const int kq   = threadIdx.x & 7;        // 4 k's each
    const uint32_t p0 = (uint32_t)__half_as_ushort(__float2half_rn(tile[kq*4+0][nloc]))
                      | ((uint32_t)__half_as_ushort(__float2half_rn(tile[kq*4+1][nloc])) << 16);
    const uint32_t p1 = (uint32_t)__half_as_ushort(__float2half_rn(tile[kq*4+2][nloc]))
                      | ((uint32_t)__half_as_ushort(__float2half_rn(tile[kq*4+3][nloc])) << 16);
    *reinterpret_cast<uint2*>(WT + (size_t)(n0 + nloc) * K + k0 + kq * 4) =
        make_uint2(p0, p1);
}

// ============================================================================
// Tridiagonal adjacency stencil + bias (+relu), output fp16
// ============================================================================
template <bool RELU>
__global__ void stencil_h(const float* __restrict__ sup,
                          const float* __restrict__ bias,
                          __half* __restrict__ outp)
{
    const int idx = blockIdx.x * blockDim.x + threadIdx.x;
    if (idx >= MTOT * (HID / 4)) return;
    const int c4  = idx % (HID / 4);
    const int row = idx / (HID / 4);
    const int s   = row % SEQ;

    const float inv2 = 0.707106781186547524f;
    const float inv3 = 0.577350269189625764f;
    const float ds   = (s == 0 || s == SEQ - 1) ? inv2 : inv3;

    const float4* base = reinterpret_cast<const float4*>(sup) + (size_t)row * (HID / 4) + c4;
    float4 cen = base[0];
    float4 a = make_float4(ds * cen.x, ds * cen.y, ds * cen.z, ds * cen.w);
    if (s > 0) {
        const float dl = (s - 1 == 0) ? inv2 : inv3;
        float4 lf = base[-(HID / 4)];
        a.x = fmaf(dl, lf.x, a.x); a.y = fmaf(dl, lf.y, a.y);
        a.z = fmaf(dl, lf.z, a.z); a.w = fmaf(dl, lf.w, a.w);
    }
    if (s < SEQ - 1) {
        const float dr = (s + 1 == SEQ - 1) ? inv2 : inv3;
        float4 rt = base[(HID / 4)];
        a.x = fmaf(dr, rt.x, a.x); a.y = fmaf(dr, rt.y, a.y);
        a.z = fmaf(dr, rt.z, a.z); a.w = fmaf(dr, rt.w, a.w);
    }
    const float4 bvec = reinterpret_cast<const float4*>(bias)[c4];
    float4 o = make_float4(fmaf(ds, a.x, bvec.x), fmaf(ds, a.y, bvec.y),
                           fmaf(ds, a.z, bvec.z), fmaf(ds, a.w, bvec.w));
    if (RELU) {
        o.x = fmaxf(o.x, 0.f); o.y = fmaxf(o.y, 0.f);
        o.z = fmaxf(o.z, 0.f); o.w = fmaxf(o.w, 0.f);
    }
    const uint32_t p0 = (uint32_t)__half_as_ushort(__float2half_rn(o.x))
                      | ((uint32_t)__half_as_ushort(__float2half_rn(o.y)) << 16);
    const uint32_t p1 = (uint32_t)__half_as_ushort(__float2half_rn(o.z))
                      | ((uint32_t)__half_as_ushort(__float2half_rn(o.w)) << 16);
    *reinterpret_cast<uint2*>(outp + (size_t)row * HID + c4 * 4) = make_uint2(p0, p1);
}

// ============================================================================
// Final head: sigmoid(z2 @ s3_W + b), K = 128, one warp per row
// ============================================================================
__global__ void head_kernel(const float* __restrict__ z2,
                            const float* __restrict__ w,
                            const float* __restrict__ b,
                            float* __restrict__ out)
{
    const int gtid = blockIdx.x * blockDim.x + threadIdx.x;
    const int row  = gtid >> 5;
    const int lane = gtid & 31;
    if (row >= MTOT) return;
    float4 wv = reinterpret_cast<const float4*>(w)[lane];
    float4 xv = reinterpret_cast<const float4*>(z2 + (size_t)row * SC2)[lane];
    float sum = xv.x * wv.x + xv.y * wv.y + xv.z * wv.z + xv.w * wv.w;
#pragma unroll
    for (int o = 16; o > 0; o >>= 1) sum += __shfl_xor_sync(0xFFFFFFFFu, sum, o);
    if (lane == 0) out[row] = 1.0f / (1.0f + expf(-(sum + b[0])));
}

// ============================================================================
extern "C" void kernel_launch(void* const* d_in, const int* in_sizes, int n_in,
                              void* d_out, int out_size)
{
    const float* x    = (const float*)d_in[0];
    const float* Wp   = (const float*)d_in[1];
    const float* bp   = (const float*)d_in[2];
    const float* gcnW = (const float*)d_in[3];
    const float* gcnb = (const float*)d_in[4];
    const float* s1W  = (const float*)d_in[5];
    const float* s1b  = (const float*)d_in[6];
    const float* s2W  = (const float*)d_in[7];
    const float* s2b  = (const float*)d_in[8];
    const float* s3W  = (const float*)d_in[9];
    const float* s3b  = (const float*)d_in[10];
    float* out = (float*)d_out;

    float *sup, *z2;
    __half *xh, *a0h, *a1h, *wpT, *gwT, *s1T, *s2T;
    cudaGetSymbolAddress((void**)&sup, g_sup);
    cudaGetSymbolAddress((void**)&z2,  g_z2);
    cudaGetSymbolAddress((void**)&xh,  g_xh);
    cudaGetSymbolAddress((void**)&a0h, g_a0h);
    cudaGetSymbolAddress((void**)&a1h, g_a1h);
    cudaGetSymbolAddress((void**)&wpT, g_wpT);
    cudaGetSymbolAddress((void**)&gwT, g_gwT);
    cudaGetSymbolAddress((void**)&s1T, g_s1T);
    cudaGetSymbolAddress((void**)&s2T, g_s2T);

    // Opt in to 65 KB dynamic smem for each GEMM instantiation
    cudaFuncSetAttribute(mma_gemm<0,1,1>, cudaFuncAttributeMaxDynamicSharedMemorySize, GEMM_SMEM);
    cudaFuncSetAttribute(mma_gemm<0,0,0>, cudaFuncAttributeMaxDynamicSharedMemorySize, GEMM_SMEM);
    cudaFuncSetAttribute(mma_gemm<1,1,1>, cudaFuncAttributeMaxDynamicSharedMemorySize, GEMM_SMEM);
    cudaFuncSetAttribute(mma_gemm<1,1,0>, cudaFuncAttributeMaxDynamicSharedMemorySize, GEMM_SMEM);

    // --- Weight transpose + fp16 conversion ---
    transpose_half_tiled<<<dim3(FIN/32, HID/32), 256>>>(Wp, wpT, FIN, HID);
    for (int i = 0; i < 3; i++)
        transpose_half_tiled<<<dim3(HID/32, HID/32), 256>>>(
            gcnW + (size_t)i*HID*HID, gwT + (size_t)i*HID*HID, HID, HID);
    transpose_half_tiled<<<dim3(HID/32, SC1/32), 256>>>(s1W, s1T, HID, SC1);
    transpose_half_tiled<<<dim3(SC1/32, SC2/32), 256>>>(s2W, s2T, SC1, SC2);

    // --- x -> fp16 ---
    {
        int n4 = MTOT * FIN / 4;
        half_convert<<<(n4+255)/256, 256>>>((const float4*)x, (uint2*)xh, n4);
    }

    const int st_blocks = (MTOT * (HID / 4) + 255) / 256;

    // 1) h0 = x @ Wp + bp  -> a0 (fp16)
    mma_gemm<0,1,1><<<dim3(HID/BN, MTOT/BM), 256, GEMM_SMEM>>>(
        xh, wpT, bp, nullptr, a0h, MTOT, HID, FIN);

    // 2) 3 GCN layers: sup = h @ W (fp32), then stencil+bias(+relu) -> a0 (fp16)
    for (int i = 0; i < 3; i++) {
        mma_gemm<0,0,0><<<dim3(HID/BN, MTOT/BM), 256, GEMM_SMEM>>>(
            a0h, gwT + (size_t)i*HID*HID, nullptr, sup, nullptr, MTOT, HID, HID);
        if (i < 2)
            stencil_h<true ><<<st_blocks, 256>>>(sup, gcnb + (size_t)i*HID, a0h);
        else
            stencil_h<false><<<st_blocks, 256>>>(sup, gcnb + (size_t)i*HID, a0h);
    }

    // 3) z1 = relu(h @ s1W + s1b) -> a1 (fp16)
    mma_gemm<1,1,1><<<dim3(SC1/BN, MTOT/BM), 256, GEMM_SMEM>>>(
        a0h, s1T, s1b, nullptr, a1h, MTOT, SC1, HID);

    // 4) z2 = relu(z1 @ s2W + s2b) -> fp32
    mma_gemm<1,1,0><<<dim3(SC2/BN, MTOT/BM), 256, GEMM_SMEM>>>(
        a1h, s2T, s2b, z2, nullptr, MTOT, SC2, SC1);

    // 5) out = sigmoid(z2 @ s3W + s3b)
    {
        const int blocks = (MTOT + 7) / 8;
        head_kernel<<<blocks, 256>>>(z2, s3W, s3b, out);
    }
}

// round 14
// speedup vs baseline: 5.8815x; 1.0588x over previous
#include <cuda_runtime.h>
#include <cuda_fp16.h>
#include <cstdint>
#include <math.h>

// Problem dims (fixed by the reference)
#define BATCH 8
#define SEQ   2048
#define FIN   1024
#define HID   512
#define SC1   256
#define SC2   128
#define MTOT  (BATCH * SEQ)   // 16384 rows

// ============================================================================
// Scratch (__device__ globals — no allocations allowed)
// ============================================================================
__device__ __half g_xh  [MTOT * FIN];    // x in fp16              (32 MB)
__device__ __half g_a0h [MTOT * HID];    // activations fp16       (16 MB)
__device__ __half g_a1h [MTOT * SC1];    // score-layer1 act fp16
__device__ __half g_suph[MTOT * HID];    // GCN support fp16       (16 MB)
__device__ __half g_wpT[HID * FIN];      // transposed fp16 weights
__device__ __half g_gwT[3 * HID * HID];
__device__ __half g_s1T[SC1 * HID];
__device__ __half g_s2T[SC2 * SC1];

// ============================================================================
// Baseline-PTX primitives (no sm_103a-only features)
// ============================================================================
__device__ __forceinline__ uint32_t smem_u32(const void* p) {
    uint32_t a;
    asm("{ .reg .u64 t; cvta.to.shared.u64 t, %1; cvt.u32.u64 %0, t; }" : "=r"(a) : "l"(p));
    return a;
}
__device__ __forceinline__ void cpasync16(uint32_t dst, const void* src) {
    asm volatile("cp.async.cg.shared.global [%0], [%1], 16;" :: "r"(dst), "l"(src) : "memory");
}
__device__ __forceinline__ void cp_commit() {
    asm volatile("cp.async.commit_group;" ::: "memory");
}
template <int N>
__device__ __forceinline__ void cp_wait() {
    asm volatile("cp.async.wait_group %0;" :: "n"(N) : "memory");
}
__device__ __forceinline__ void ldm_x4(uint32_t* r, uint32_t addr) {
    asm volatile("ldmatrix.sync.aligned.m8n8.x4.shared.b16 {%0,%1,%2,%3}, [%4];"
        : "=r"(r[0]), "=r"(r[1]), "=r"(r[2]), "=r"(r[3]) : "r"(addr));
}
// m16n8k16 fp16 MMA, fp32 accumulate
__device__ __forceinline__ void mma16816(float* c, const uint32_t* a, const uint32_t* b) {
    asm volatile(
        "mma.sync.aligned.m16n8k16.row.col.f32.f16.f16.f32 "
        "{%0,%1,%2,%3}, {%4,%5,%6,%7}, {%8,%9}, {%0,%1,%2,%3};"
        : "+f"(c[0]), "+f"(c[1]), "+f"(c[2]), "+f"(c[3])
        : "r"(a[0]), "r"(a[1]), "r"(a[2]), "r"(a[3]), "r"(b[0]), "r"(b[1]));
}

// SMEM tile: 128 rows x 64 fp16 (128 B/row = 8 x 16B chunks). XOR swizzle keeps
// cp.async stores and ldmatrix loads bank-conflict-free:
//   offset = r*128 + ((c16 ^ (r & 7)) << 4)
__device__ __forceinline__ uint32_t swz(int r, int c16) {
    return (uint32_t)(r * 128 + (((c16) ^ (r & 7)) << 4));
}

// ============================================================================
// fp16 single-pass GEMM: C[M,N] = A[M,K] @ B[N,K]^T, fp32 accumulate.
// BM=BN=128, BK=64, 256 threads (8 warps, 4x2), warp tile 32x64.
// 3-stage cp.async pipeline; epilogue staged through SMEM.
// OUTMODE 0: fp32 C.  OUTMODE 1: fp16 C.  OUTMODE 2: fused score head
//   (bias+relu then row-dot with W3, +B3, sigmoid -> Cf[row]).
// ============================================================================
#define BM 128
#define BN 128
#define BKC 64
#define ABUF 16384             // bytes per fp16 tile (128 rows * 128 B)
#define STAGE (2 * ABUF)       // A + B = 32 KB
#define NSTAGE 3
#define GEMM_SMEM (NSTAGE * STAGE)   // 98304 B (>= epi 128*130*4 = 66560)
#define EPI_STRIDE 130         // padded fp32 row stride for epilogue staging

template <int ACT, int HASBIAS, int OUTMODE>
__global__ __launch_bounds__(256, 2)
void mma_gemm(const __half* __restrict__ A, const __half* __restrict__ B,
              const float* __restrict__ bias,
              float* __restrict__ Cf, __half* __restrict__ Ch,
              const float* __restrict__ W3, const float* __restrict__ B3,
              int M, int N, int K)
{
    extern __shared__ char smem[];
    const uint32_t sb = smem_u32(smem);
    const int tid = threadIdx.x;
    const int wid = tid >> 5, lid = tid & 31;
    const int wm = wid & 3, wn = wid >> 2;          // 4 x 2 warp grid
    const int m0 = blockIdx.y * BM, n0 = blockIdx.x * BN;

    // cp.async g2s for one K-chunk (64 halves) into one stage (A tile + B tile)
    auto g2s = [&](int c, int st) {
        const uint32_t base = sb + st * STAGE;
        const __half* srcA = A + (size_t)m0 * K + c * BKC;
        const __half* srcB = B + (size_t)n0 * K + c * BKC;
#pragma unroll
        for (int i = 0; i < 4; i++) {
            const int q = tid + i * 256;              // 0..1023
            const int r = q >> 3, c16 = q & 7;
            const uint32_t so = swz(r, c16);
            cpasync16(base + so,        srcA + (size_t)r * K + c16 * 8);
            cpasync16(base + ABUF + so, srcB + (size_t)r * K + c16 * 8);
        }
    };

    float acc[2][8][4];
#pragma unroll
    for (int i = 0; i < 2; i++)
#pragma unroll
        for (int j = 0; j < 8; j++)
#pragma unroll
            for (int q = 0; q < 4; q++) acc[i][j][q] = 0.0f;

    // ldmatrix lane decomposition
    const int lt = lid >> 3;         // tile index 0..3 within x4
    const int lj = lid & 7;          // row within 8x8 tile

    const int NC = K / BKC;          // >= 4 for all layers
    g2s(0, 0); cp_commit();
    if (NC > 1) g2s(1, 1);
    cp_commit();

    for (int c = 0; c < NC; c++) {
        cp_wait<1>();                 // stage c landed
        __syncthreads();              // all warps see it; prior stage reads done
        if (c + 2 < NC) g2s(c + 2, (c + 2) % NSTAGE);
        cp_commit();                  // always commit to keep group count fixed

        const uint32_t stg = sb + (c % NSTAGE) * STAGE;
        const uint32_t sA = stg, sB = stg + ABUF;

#pragma unroll
        for (int kk = 0; kk < BKC; kk += 16) {
            // A fragments (m16k16): x4 tiles (m0k0, m8k0, m0k8, m8k8)
            uint32_t a[2][4];
#pragma unroll
            for (int mi = 0; mi < 2; mi++) {
                const int rowA = wm * 32 + mi * 16 + lj + ((lt & 1) << 3);
                ldm_x4(a[mi], sA + swz(rowA, (kk >> 3) + (lt >> 1)));
            }
            // B fragments (two n8k16 per x4): tiles (n0k0, n0k8, n8k0, n8k8)
            uint32_t bf[4][4];
#pragma unroll
            for (int nb = 0; nb < 4; nb++) {
                const int rowB = wn * 64 + nb * 16 + lj + ((lt >> 1) << 3);
                ldm_x4(bf[nb], sB + swz(rowB, (kk >> 3) + (lt & 1)));
            }
            // single-pass fp16 MMA
#pragma unroll
            for (int mi = 0; mi < 2; mi++)
#pragma unroll
                for (int nb = 0; nb < 4; nb++) {
                    mma16816(acc[mi][2 * nb],     a[mi], &bf[nb][0]);
                    mma16816(acc[mi][2 * nb + 1], a[mi], &bf[nb][2]);
                }
        }
    }

    // ---------------- Epilogue (staged through SMEM) ------------------------
    __syncthreads();                       // all warps done reading stages
    float* sc = reinterpret_cast<float*>(smem);
    {
        const int tq = lid >> 2, tr = lid & 3;
#pragma unroll
        for (int ni = 0; ni < 8; ni++) {
            const int col = wn * 64 + ni * 8 + tr * 2;
#pragma unroll
            for (int mi = 0; mi < 2; mi++) {
                const int row = wm * 32 + mi * 16 + tq;
                sc[row * EPI_STRIDE + col]           = acc[mi][ni][0];
                sc[row * EPI_STRIDE + col + 1]       = acc[mi][ni][1];
                sc[(row + 8) * EPI_STRIDE + col]     = acc[mi][ni][2];
                sc[(row + 8) * EPI_STRIDE + col + 1] = acc[mi][ni][3];
            }
        }
    }
    __syncthreads();

    if (OUTMODE == 2) {
        // Fused score head: v = relu(z + b2); out[row] = sigmoid(dot(v, W3) + b3)
        const float4 wv = *reinterpret_cast<const float4*>(W3 + lid * 4);
        const float4 bb = *reinterpret_cast<const float4*>(bias + lid * 4);
        const float b3 = B3[0];
#pragma unroll
        for (int i = 0; i < 16; i++) {
            const int r = wid * 16 + i;
            const float* sp = sc + r * EPI_STRIDE + lid * 4;
            const float v0 = fmaxf(sp[0] + bb.x, 0.f);
            const float v1 = fmaxf(sp[1] + bb.y, 0.f);
            const float v2 = fmaxf(sp[2] + bb.z, 0.f);
            const float v3 = fmaxf(sp[3] + bb.w, 0.f);
            float sum = v0 * wv.x + v1 * wv.y + v2 * wv.z + v3 * wv.w;
#pragma unroll
            for (int o = 16; o > 0; o >>= 1) sum += __shfl_xor_sync(0xFFFFFFFFu, sum, o);
            if (lid == 0) Cf[m0 + r] = 1.0f / (1.0f + expf(-(sum + b3)));
        }
    } else {
        // Each warp writes 16 rows; lane l handles 4 consecutive columns.
        const int cl = lid * 4;
        float b0 = 0.f, b1 = 0.f, b2 = 0.f, b3 = 0.f;
        if (HASBIAS) {
            const float4 bv = *reinterpret_cast<const float4*>(bias + n0 + cl);
            b0 = bv.x; b1 = bv.y; b2 = bv.z; b3 = bv.w;
        }
#pragma unroll
        for (int i = 0; i < 16; i++) {
            const int r = wid * 16 + i;
            const float* sp = sc + r * EPI_STRIDE + cl;
            float v0 = sp[0] + b0, v1 = sp[1] + b1, v2 = sp[2] + b2, v3 = sp[3] + b3;
            if (ACT) {
                v0 = fmaxf(v0, 0.f); v1 = fmaxf(v1, 0.f);
                v2 = fmaxf(v2, 0.f); v3 = fmaxf(v3, 0.f);
            }
            const size_t base = (size_t)(m0 + r) * N + n0 + cl;
            if (OUTMODE == 0) {
                *reinterpret_cast<float4*>(Cf + base) = make_float4(v0, v1, v2, v3);
            } else {
                const uint32_t p0 = (uint32_t)__half_as_ushort(__float2half_rn(v0))
                                  | ((uint32_t)__half_as_ushort(__float2half_rn(v1)) << 16);
                const uint32_t p1 = (uint32_t)__half_as_ushort(__float2half_rn(v2))
                                  | ((uint32_t)__half_as_ushort(__float2half_rn(v3)) << 16);
                *reinterpret_cast<uint2*>(Ch + base) = make_uint2(p0, p1);
            }
        }
    }
}

// ============================================================================
// Elementwise converters
// ============================================================================
// x: fp32 -> fp16
__global__ void half_convert(const float4* __restrict__ in,
                             uint2* __restrict__ outp, int n4)
{
    const int i = blockIdx.x * blockDim.x + threadIdx.x;
    if (i >= n4) return;
    const float4 v = in[i];
    const uint32_t p0 = (uint32_t)__half_as_ushort(__float2half_rn(v.x))
                      | ((uint32_t)__half_as_ushort(__float2half_rn(v.y)) << 16);
    const uint32_t p1 = (uint32_t)__half_as_ushort(__float2half_rn(v.z))
                      | ((uint32_t)__half_as_ushort(__float2half_rn(v.w)) << 16);
    outp[i] = make_uint2(p0, p1);
}

// Tiled W [K,N] fp32 -> WT [N,K] fp16. 32x32 tiles via smem.
__global__ void transpose_half_tiled(const float* __restrict__ W,
                                     __half* __restrict__ WT, int K, int N)
{
    __shared__ float tile[32][33];
    const int k0 = blockIdx.x * 32, n0 = blockIdx.y * 32;
    {
        const int c = threadIdx.x & 31, r8 = threadIdx.x >> 5;
#pragma unroll
        for (int r = r8; r < 32; r += 8)
            tile[r][c] = W[(size_t)(k0 + r) * N + n0 + c];
    }
    __syncthreads();
    const int nloc = threadIdx.x >> 3;       // 0..31
    const int kq   = threadIdx.x & 7;        // 4 k's each
    const uint32_t p0 = (uint32_t)__half_as_ushort(__float2half_rn(tile[kq*4+0][nloc]))
                      | ((uint32_t)__half_as_ushort(__float2half_rn(tile[kq*4+1][nloc])) << 16);
    const uint32_t p1 = (uint32_t)__half_as_ushort(__float2half_rn(tile[kq*4+2][nloc]))
                      | ((uint32_t)__half_as_ushort(__float2half_rn(tile[kq*4+3][nloc])) << 16);
    *reinterpret_cast<uint2*>(WT + (size_t)(n0 + nloc) * K + k0 + kq * 4) =
        make_uint2(p0, p1);
}

// ============================================================================
// Tridiagonal adjacency stencil + bias (+relu): fp16 in -> fp16 out, fp32 math
// ============================================================================
__device__ __forceinline__ void unpack8(const uint4 u, float* f) {
    const __half2* h = reinterpret_cast<const __half2*>(&u);
#pragma unroll
    for (int j = 0; j < 4; j++) {
        const float2 t = __half22float2(h[j]);
        f[2 * j] = t.x; f[2 * j + 1] = t.y;
    }
}

template <bool RELU>
__global__ void stencil_h(const __half* __restrict__ sup,
                          const float* __restrict__ bias,
                          __half* __restrict__ outp)
{
    const int idx = blockIdx.x * blockDim.x + threadIdx.x;
    if (idx >= MTOT * (HID / 8)) return;
    const int c8  = idx % (HID / 8);
    const int row = idx / (HID / 8);
    const int s   = row % SEQ;

    const float inv2 = 0.707106781186547524f;
    const float inv3 = 0.577350269189625764f;
    const float ds   = (s == 0 || s == SEQ - 1) ? inv2 : inv3;

    const uint4* base = reinterpret_cast<const uint4*>(sup) + (size_t)row * (HID / 8) + c8;
    float cen[8], nb[8], a[8];
    unpack8(base[0], cen);
#pragma unroll
    for (int j = 0; j < 8; j++) a[j] = ds * cen[j];
    if (s > 0) {
        const float dl = (s - 1 == 0) ? inv2 : inv3;
        unpack8(base[-(HID / 8)], nb);
#pragma unroll
        for (int j = 0; j < 8; j++) a[j] = fmaf(dl, nb[j], a[j]);
    }
    if (s < SEQ - 1) {
        const float dr = (s + 1 == SEQ - 1) ? inv2 : inv3;
        unpack8(base[(HID / 8)], nb);
#pragma unroll
        for (int j = 0; j < 8; j++) a[j] = fmaf(dr, nb[j], a[j]);
    }
    const float4 bv0 = reinterpret_cast<const float4*>(bias)[c8 * 2];
    const float4 bv1 = reinterpret_cast<const float4*>(bias)[c8 * 2 + 1];
    const float bb[8] = {bv0.x, bv0.y, bv0.z, bv0.w, bv1.x, bv1.y, bv1.z, bv1.w};
    uint32_t p[4];
#pragma unroll
    for (int j = 0; j < 4; j++) {
        float o0 = fmaf(ds, a[2*j],   bb[2*j]);
        float o1 = fmaf(ds, a[2*j+1], bb[2*j+1]);
        if (RELU) { o0 = fmaxf(o0, 0.f); o1 = fmaxf(o1, 0.f); }
        p[j] = (uint32_t)__half_as_ushort(__float2half_rn(o0))
             | ((uint32_t)__half_as_ushort(__float2half_rn(o1)) << 16);
    }
    reinterpret_cast<uint4*>(outp)[(size_t)row * (HID / 8) + c8] =
        make_uint4(p[0], p[1], p[2], p[3]);
}

// ============================================================================
extern "C" void kernel_launch(void* const* d_in, const int* in_sizes, int n_in,
                              void* d_out, int out_size)
{
    const float* x    = (const float*)d_in[0];
    const float* Wp   = (const float*)d_in[1];
    const float* bp   = (const float*)d_in[2];
    const float* gcnW = (const float*)d_in[3];
    const float* gcnb = (const float*)d_in[4];
    const float* s1W  = (const float*)d_in[5];
    const float* s1b  = (const float*)d_in[6];
    const float* s2W  = (const float*)d_in[7];
    const float* s2b  = (const float*)d_in[8];
    const float* s3W  = (const float*)d_in[9];
    const float* s3b  = (const float*)d_in[10];
    float* out = (float*)d_out;

    __half *xh, *a0h, *a1h, *suph, *wpT, *gwT, *s1T, *s2T;
    cudaGetSymbolAddress((void**)&xh,   g_xh);
    cudaGetSymbolAddress((void**)&a0h,  g_a0h);
    cudaGetSymbolAddress((void**)&a1h,  g_a1h);
    cudaGetSymbolAddress((void**)&suph, g_suph);
    cudaGetSymbolAddress((void**)&wpT,  g_wpT);
    cudaGetSymbolAddress((void**)&gwT,  g_gwT);
    cudaGetSymbolAddress((void**)&s1T,  g_s1T);
    cudaGetSymbolAddress((void**)&s2T,  g_s2T);

    // Opt in to 96 KB dynamic smem for each GEMM instantiation
    cudaFuncSetAttribute(mma_gemm<0,1,1>, cudaFuncAttributeMaxDynamicSharedMemorySize, GEMM_SMEM);
    cudaFuncSetAttribute(mma_gemm<0,0,1>, cudaFuncAttributeMaxDynamicSharedMemorySize, GEMM_SMEM);
    cudaFuncSetAttribute(mma_gemm<1,1,1>, cudaFuncAttributeMaxDynamicSharedMemorySize, GEMM_SMEM);
    cudaFuncSetAttribute(mma_gemm<1,1,2>, cudaFuncAttributeMaxDynamicSharedMemorySize, GEMM_SMEM);

    // --- Weight transpose + fp16 conversion ---
    transpose_half_tiled<<<dim3(FIN/32, HID/32), 256>>>(Wp, wpT, FIN, HID);
    for (int i = 0; i < 3; i++)
        transpose_half_tiled<<<dim3(HID/32, HID/32), 256>>>(
            gcnW + (size_t)i*HID*HID, gwT + (size_t)i*HID*HID, HID, HID);
    transpose_half_tiled<<<dim3(HID/32, SC1/32), 256>>>(s1W, s1T, HID, SC1);
    transpose_half_tiled<<<dim3(SC1/32, SC2/32), 256>>>(s2W, s2T, SC1, SC2);

    // --- x -> fp16 ---
    {
        int n4 = MTOT * FIN / 4;
        half_convert<<<(n4+255)/256, 256>>>((const float4*)x, (uint2*)xh, n4);
    }

    const int st_blocks = (MTOT * (HID / 8) + 255) / 256;

    // 1) h0 = x @ Wp + bp  -> a0 (fp16)
    mma_gemm<0,1,1><<<dim3(HID/BN, MTOT/BM), 256, GEMM_SMEM>>>(
        xh, wpT, bp, nullptr, a0h, nullptr, nullptr, MTOT, HID, FIN);

    // 2) 3 GCN layers: sup = h @ W (fp16), then stencil+bias(+relu) -> a0 (fp16)
    for (int i = 0; i < 3; i++) {
        mma_gemm<0,0,1><<<dim3(HID/BN, MTOT/BM), 256, GEMM_SMEM>>>(
            a0h, gwT + (size_t)i*HID*HID, nullptr, nullptr, suph, nullptr, nullptr,
            MTOT, HID, HID);
        if (i < 2)
            stencil_h<true ><<<st_blocks, 256>>>(suph, gcnb + (size_t)i*HID, a0h);
        else
            stencil_h<false><<<st_blocks, 256>>>(suph, gcnb + (size_t)i*HID, a0h);
    }

    // 3) z1 = relu(h @ s1W + s1b) -> a1 (fp16)
    mma_gemm<1,1,1><<<dim3(SC1/BN, MTOT/BM), 256, GEMM_SMEM>>>(
        a0h, s1T, s1b, nullptr, a1h, nullptr, nullptr, MTOT, SC1, HID);

    // 4+5) out = sigmoid(relu(z1 @ s2W + s2b) @ s3W + s3b)  (fused head epilogue)
    mma_gemm<1,1,2><<<dim3(SC2/BN, MTOT/BM), 256, GEMM_SMEM>>>(
        a1h, s2T, s2b, out, nullptr, s3W, s3b, MTOT, SC2, SC1);
}

// round 16
// speedup vs baseline: 6.6425x; 1.1294x over previous
#include <cuda_runtime.h>
#include <cuda_fp16.h>
#include <cstdint>
#include <math.h>

// Problem dims (fixed by the reference)
#define BATCH 8
#define SEQ   2048
#define FIN   1024
#define HID   512
#define SC1   256
#define SC2   128
#define MTOT  (BATCH * SEQ)   // 16384 rows

// ============================================================================
// Scratch (__device__ globals — no allocations allowed)
// ============================================================================
__device__ __half g_xh  [MTOT * FIN];    // x in fp16              (32 MB)
__device__ __half g_a0h [MTOT * HID];    // activations fp16       (16 MB)
__device__ __half g_a1h [MTOT * SC1];    // score-layer1 act fp16
__device__ __half g_suph[MTOT * HID];    // GCN support fp16       (16 MB)
__device__ __half g_wpT[HID * FIN];      // transposed fp16 weights
__device__ __half g_gwT[3 * HID * HID];
__device__ __half g_s1T[SC1 * HID];
__device__ __half g_s2T[SC2 * SC1];

// ============================================================================
// Baseline-PTX primitives (no sm_103a-only features)
// ============================================================================
__device__ __forceinline__ uint32_t smem_u32(const void* p) {
    uint32_t a;
    asm("{ .reg .u64 t; cvta.to.shared.u64 t, %1; cvt.u32.u64 %0, t; }" : "=r"(a) : "l"(p));
    return a;
}
__device__ __forceinline__ void cpasync16(uint32_t dst, const void* src) {
    asm volatile("cp.async.cg.shared.global [%0], [%1], 16;" :: "r"(dst), "l"(src) : "memory");
}
__device__ __forceinline__ void cp_commit() {
    asm volatile("cp.async.commit_group;" ::: "memory");
}
template <int N>
__device__ __forceinline__ void cp_wait() {
    asm volatile("cp.async.wait_group %0;" :: "n"(N) : "memory");
}
__device__ __forceinline__ void ldm_x4(uint32_t* r, uint32_t addr) {
    asm volatile("ldmatrix.sync.aligned.m8n8.x4.shared.b16 {%0,%1,%2,%3}, [%4];"
        : "=r"(r[0]), "=r"(r[1]), "=r"(r[2]), "=r"(r[3]) : "r"(addr));
}
// m16n8k16 fp16 MMA, fp32 accumulate
__device__ __forceinline__ void mma16816(float* c, const uint32_t* a, const uint32_t* b) {
    asm volatile(
        "mma.sync.aligned.m16n8k16.row.col.f32.f16.f16.f32 "
        "{%0,%1,%2,%3}, {%4,%5,%6,%7}, {%8,%9}, {%0,%1,%2,%3};"
        : "+f"(c[0]), "+f"(c[1]), "+f"(c[2]), "+f"(c[3])
        : "r"(a[0]), "r"(a[1]), "r"(a[2]), "r"(a[3]), "r"(b[0]), "r"(b[1]));
}
__device__ __forceinline__ uint32_t packh2(float a, float b) {
    return (uint32_t)__half_as_ushort(__float2half_rn(a))
         | ((uint32_t)__half_as_ushort(__float2half_rn(b)) << 16);
}

// SMEM tile: 128 rows x 64 fp16 (128 B/row = 8 x 16B chunks). XOR swizzle keeps
// cp.async stores and ldmatrix loads bank-conflict-free:
//   offset = r*128 + ((c16 ^ (r & 7)) << 4)
__device__ __forceinline__ uint32_t swz(int r, int c16) {
    return (uint32_t)(r * 128 + (((c16) ^ (r & 7)) << 4));
}

// ============================================================================
// fp16 single-pass GEMM: C[M,N] = A[M,K] @ B[N,K]^T, fp32 accumulate.
// BM=BN=128, BK=64, 256 threads (8 warps, 4x2), warp tile 32x64.
// 3-stage cp.async pipeline; epilogue staged through SMEM.
// OUTMODE 0: fp32 C.  OUTMODE 1: fp16 C (fp16 smem staging).  OUTMODE 2: fused
//   score head (bias+relu then row-dot with W3, +B3, sigmoid -> Cf[row]).
// ============================================================================
#define BM 128
#define BN 128
#define BKC 64
#define ABUF 16384             // bytes per fp16 tile (128 rows * 128 B)
#define STAGE (2 * ABUF)       // A + B = 32 KB
#define NSTAGE 3
#define GEMM_SMEM (NSTAGE * STAGE)   // 98304 B (>= epi 128*132*2 / 128*130*4)
#define EPI_STRIDE 130         // fp32 stride (OUTMODE 0/2)
#define EPI_STRIDE_H 132       // fp16 stride in halves (OUTMODE 1), 264 B/row

template <int ACT, int HASBIAS, int OUTMODE>
__global__ __launch_bounds__(256, 2)
void mma_gemm(const __half* __restrict__ A, const __half* __restrict__ B,
              const float* __restrict__ bias,
              float* __restrict__ Cf, __half* __restrict__ Ch,
              const float* __restrict__ W3, const float* __restrict__ B3,
              int M, int N, int K)
{
    extern __shared__ char smem[];
    const uint32_t sb = smem_u32(smem);
    const int tid = threadIdx.x;
    const int wid = tid >> 5, lid = tid & 31;
    const int wm = wid & 3, wn = wid >> 2;          // 4 x 2 warp grid
    const int m0 = blockIdx.y * BM, n0 = blockIdx.x * BN;

    // cp.async g2s for one K-chunk (64 halves) into one stage (A tile + B tile)
    auto g2s = [&](int c, int st) {
        const uint32_t base = sb + st * STAGE;
        const __half* srcA = A + (size_t)m0 * K + c * BKC;
        const __half* srcB = B + (size_t)n0 * K + c * BKC;
#pragma unroll
        for (int i = 0; i < 4; i++) {
            const int q = tid + i * 256;              // 0..1023
            const int r = q >> 3, c16 = q & 7;
            const uint32_t so = swz(r, c16);
            cpasync16(base + so,        srcA + (size_t)r * K + c16 * 8);
            cpasync16(base + ABUF + so, srcB + (size_t)r * K + c16 * 8);
        }
    };

    float acc[2][8][4];
#pragma unroll
    for (int i = 0; i < 2; i++)
#pragma unroll
        for (int j = 0; j < 8; j++)
#pragma unroll
            for (int q = 0; q < 4; q++) acc[i][j][q] = 0.0f;

    // ldmatrix lane decomposition
    const int lt = lid >> 3;         // tile index 0..3 within x4
    const int lj = lid & 7;          // row within 8x8 tile

    const int NC = K / BKC;          // >= 4 for all layers
    g2s(0, 0); cp_commit();
    if (NC > 1) g2s(1, 1);
    cp_commit();

    for (int c = 0; c < NC; c++) {
        cp_wait<1>();                 // stage c landed
        __syncthreads();              // all warps see it; prior stage reads done
        if (c + 2 < NC) g2s(c + 2, (c + 2) % NSTAGE);
        cp_commit();                  // always commit to keep group count fixed

        const uint32_t stg = sb + (c % NSTAGE) * STAGE;
        const uint32_t sA = stg, sB = stg + ABUF;

#pragma unroll
        for (int kk = 0; kk < BKC; kk += 16) {
            // A fragments (m16k16): x4 tiles (m0k0, m8k0, m0k8, m8k8)
            uint32_t a[2][4];
#pragma unroll
            for (int mi = 0; mi < 2; mi++) {
                const int rowA = wm * 32 + mi * 16 + lj + ((lt & 1) << 3);
                ldm_x4(a[mi], sA + swz(rowA, (kk >> 3) + (lt >> 1)));
            }
            // B fragments (two n8k16 per x4): tiles (n0k0, n0k8, n8k0, n8k8)
            uint32_t bf[4][4];
#pragma unroll
            for (int nb = 0; nb < 4; nb++) {
                const int rowB = wn * 64 + nb * 16 + lj + ((lt >> 1) << 3);
                ldm_x4(bf[nb], sB + swz(rowB, (kk >> 3) + (lt & 1)));
            }
            // single-pass fp16 MMA
#pragma unroll
            for (int mi = 0; mi < 2; mi++)
#pragma unroll
                for (int nb = 0; nb < 4; nb++) {
                    mma16816(acc[mi][2 * nb],     a[mi], &bf[nb][0]);
                    mma16816(acc[mi][2 * nb + 1], a[mi], &bf[nb][2]);
                }
        }
    }

    // ---------------- Epilogue (staged through SMEM) ------------------------
    __syncthreads();                       // all warps done reading stages

    if (OUTMODE == 1) {
        // Stage as fp16 (bias+relu applied pre-store): half the smem traffic.
        uint32_t* sh = reinterpret_cast<uint32_t*>(smem);
        const int tq = lid >> 2, tr = lid & 3;
#pragma unroll
        for (int ni = 0; ni < 8; ni++) {
            const int col = wn * 64 + ni * 8 + tr * 2;
            float b0 = 0.f, b1 = 0.f;
            if (HASBIAS) { b0 = bias[n0 + col]; b1 = bias[n0 + col + 1]; }
#pragma unroll
            for (int mi = 0; mi < 2; mi++) {
                const int row = wm * 32 + mi * 16 + tq;
                float v0 = acc[mi][ni][0] + b0, v1 = acc[mi][ni][1] + b1;
                float v2 = acc[mi][ni][2] + b0, v3 = acc[mi][ni][3] + b1;
                if (ACT) {
                    v0 = fmaxf(v0, 0.f); v1 = fmaxf(v1, 0.f);
                    v2 = fmaxf(v2, 0.f); v3 = fmaxf(v3, 0.f);
                }
                sh[(row * EPI_STRIDE_H + col) >> 1]       = packh2(v0, v1);
                sh[((row + 8) * EPI_STRIDE_H + col) >> 1] = packh2(v2, v3);
            }
        }
        __syncthreads();
        // Each warp writes 16 rows; lane l handles 4 consecutive halves (8 B).
        // 32 lanes * 4 halves = 128 columns = BN exactly.
        const int cl = lid * 2;      // in u32 units (2 halves each)
#pragma unroll
        for (int i = 0; i < 16; i++) {
            const int r = wid * 16 + i;
            const uint32_t* sp = sh + ((r * EPI_STRIDE_H) >> 1) + cl;
            *reinterpret_cast<uint2*>(Ch + (size_t)(m0 + r) * N + n0 + cl * 2) =
                make_uint2(sp[0], sp[1]);
        }
    } else {
        float* sc = reinterpret_cast<float*>(smem);
        {
            const int tq = lid >> 2, tr = lid & 3;
#pragma unroll
            for (int ni = 0; ni < 8; ni++) {
                const int col = wn * 64 + ni * 8 + tr * 2;
#pragma unroll
                for (int mi = 0; mi < 2; mi++) {
                    const int row = wm * 32 + mi * 16 + tq;
                    sc[row * EPI_STRIDE + col]           = acc[mi][ni][0];
                    sc[row * EPI_STRIDE + col + 1]       = acc[mi][ni][1];
                    sc[(row + 8) * EPI_STRIDE + col]     = acc[mi][ni][2];
                    sc[(row + 8) * EPI_STRIDE + col + 1] = acc[mi][ni][3];
                }
            }
        }
        __syncthreads();

        if (OUTMODE == 2) {
            // Fused head: v = relu(z + b2); out[row] = sigmoid(dot(v, W3) + b3)
            const float4 wv = *reinterpret_cast<const float4*>(W3 + lid * 4);
            const float4 bb = *reinterpret_cast<const float4*>(bias + lid * 4);
            const float b3 = B3[0];
#pragma unroll
            for (int i = 0; i < 16; i++) {
                const int r = wid * 16 + i;
                const float* sp = sc + r * EPI_STRIDE + lid * 4;
                const float v0 = fmaxf(sp[0] + bb.x, 0.f);
                const float v1 = fmaxf(sp[1] + bb.y, 0.f);
                const float v2 = fmaxf(sp[2] + bb.z, 0.f);
                const float v3 = fmaxf(sp[3] + bb.w, 0.f);
                float sum = v0 * wv.x + v1 * wv.y + v2 * wv.z + v3 * wv.w;
#pragma unroll
                for (int o = 16; o > 0; o >>= 1)
                    sum += __shfl_xor_sync(0xFFFFFFFFu, sum, o);
                if (lid == 0) Cf[m0 + r] = 1.0f / (1.0f + expf(-(sum + b3)));
            }
        } else {
            const int cl = lid * 4;
            float b0 = 0.f, b1 = 0.f, b2 = 0.f, b3 = 0.f;
            if (HASBIAS) {
                const float4 bv = *reinterpret_cast<const float4*>(bias + n0 + cl);
                b0 = bv.x; b1 = bv.y; b2 = bv.z; b3 = bv.w;
            }
#pragma unroll
            for (int i = 0; i < 16; i++) {
                const int r = wid * 16 + i;
                const float* sp = sc + r * EPI_STRIDE + cl;
                float v0 = sp[0] + b0, v1 = sp[1] + b1, v2 = sp[2] + b2, v3 = sp[3] + b3;
                if (ACT) {
                    v0 = fmaxf(v0, 0.f); v1 = fmaxf(v1, 0.f);
                    v2 = fmaxf(v2, 0.f); v3 = fmaxf(v3, 0.f);
                }
                *reinterpret_cast<float4*>(Cf + (size_t)(m0 + r) * N + n0 + cl) =
                    make_float4(v0, v1, v2, v3);
            }
        }
    }
}

// ============================================================================
// Batched weight prep: ALL 6 transposes in ONE launch (block-range job table).
// Each 32x32 tile: coalesced fp32 reads, packed fp16 8B writes.
// ============================================================================
#define T_WP0   0
#define T_GW0   512          // Wp: (1024/32)*(512/32) = 512 tiles
#define T_GW1   768          // each gcn: 16*16 = 256
#define T_GW2   1024
#define T_S1    1280
#define T_S2    1408         // s1: 16*8 = 128
#define T_END   1440         // s2: 8*4 = 32

__global__ __launch_bounds__(256)
void prep_weights(const float* __restrict__ Wp, const float* __restrict__ gcnW,
                  const float* __restrict__ s1W, const float* __restrict__ s2W,
                  __half* __restrict__ wpT, __half* __restrict__ gwT,
                  __half* __restrict__ s1T, __half* __restrict__ s2T)
{
    __shared__ float tile[32][33];
    const int b = blockIdx.x;
    const float* W; __half* WT; int K, N, lt;
    if (b < T_GW0)      { W = Wp;  WT = wpT; K = FIN; N = HID; lt = b; }
    else if (b < T_GW1) { W = gcnW;                 WT = gwT;                 K = HID; N = HID; lt = b - T_GW0; }
    else if (b < T_GW2) { W = gcnW + HID*HID;       WT = gwT + HID*HID;       K = HID; N = HID; lt = b - T_GW1; }
    else if (b < T_S1)  { W = gcnW + 2*HID*HID;     WT = gwT + 2*HID*HID;     K = HID; N = HID; lt = b - T_GW2; }
    else if (b < T_S2)  { W = s1W; WT = s1T; K = HID; N = SC1; lt = b - T_S1; }
    else                { W = s2W; WT = s2T; K = SC1; N = SC2; lt = b - T_S2; }
    const int kt = K / 32;
    const int k0 = (lt % kt) * 32, n0 = (lt / kt) * 32;
    {
        const int c = threadIdx.x & 31, r8 = threadIdx.x >> 5;
#pragma unroll
        for (int r = r8; r < 32; r += 8)
            tile[r][c] = W[(size_t)(k0 + r) * N + n0 + c];
    }
    __syncthreads();
    const int nloc = threadIdx.x >> 3;       // 0..31
    const int kq   = threadIdx.x & 7;        // 4 k's each
    const uint32_t p0 = packh2(tile[kq*4+0][nloc], tile[kq*4+1][nloc]);
    const uint32_t p1 = packh2(tile[kq*4+2][nloc], tile[kq*4+3][nloc]);
    *reinterpret_cast<uint2*>(WT + (size_t)(n0 + nloc) * K + k0 + kq * 4) =
        make_uint2(p0, p1);
}

// x: fp32 -> fp16 (big, bandwidth-bound, stays separate)
__global__ void half_convert(const float4* __restrict__ in,
                             uint2* __restrict__ outp, int n4)
{
    const int i = blockIdx.x * blockDim.x + threadIdx.x;
    if (i >= n4) return;
    const float4 v = in[i];
    outp[i] = make_uint2(packh2(v.x, v.y), packh2(v.z, v.w));
}

// ============================================================================
// Tridiagonal adjacency stencil + bias (+relu): fp16 in -> fp16 out, fp32 math
// ============================================================================
__device__ __forceinline__ void unpack8(const uint4 u, float* f) {
    const __half2* h = reinterpret_cast<const __half2*>(&u);
#pragma unroll
    for (int j = 0; j < 4; j++) {
        const float2 t = __half22float2(h[j]);
        f[2 * j] = t.x; f[2 * j + 1] = t.y;
    }
}

template <bool RELU>
__global__ void stencil_h(const __half* __restrict__ sup,
                          const float* __restrict__ bias,
                          __half* __restrict__ outp)
{
    const int idx = blockIdx.x * blockDim.x + threadIdx.x;
    if (idx >= MTOT * (HID / 8)) return;
    const int c8  = idx % (HID / 8);
    const int row = idx / (HID / 8);
    const int s   = row % SEQ;

    const float inv2 = 0.707106781186547524f;
    const float inv3 = 0.577350269189625764f;
    const float ds   = (s == 0 || s == SEQ - 1) ? inv2 : inv3;

    const uint4* base = reinterpret_cast<const uint4*>(sup) + (size_t)row * (HID / 8) + c8;
    float cen[8], nb[8], a[8];
    unpack8(base[0], cen);
#pragma unroll
    for (int j = 0; j < 8; j++) a[j] = ds * cen[j];
    if (s > 0) {
        const float dl = (s - 1 == 0) ? inv2 : inv3;
        unpack8(base[-(HID / 8)], nb);
#pragma unroll
        for (int j = 0; j < 8; j++) a[j] = fmaf(dl, nb[j], a[j]);
    }
    if (s < SEQ - 1) {
        const float dr = (s + 1 == SEQ - 1) ? inv2 : inv3;
        unpack8(base[(HID / 8)], nb);
#pragma unroll
        for (int j = 0; j < 8; j++) a[j] = fmaf(dr, nb[j], a[j]);
    }
    const float4 bv0 = reinterpret_cast<const float4*>(bias)[c8 * 2];
    const float4 bv1 = reinterpret_cast<const float4*>(bias)[c8 * 2 + 1];
    const float bb[8] = {bv0.x, bv0.y, bv0.z, bv0.w, bv1.x, bv1.y, bv1.z, bv1.w};
    uint32_t p[4];
#pragma unroll
    for (int j = 0; j < 4; j++) {
        float o0 = fmaf(ds, a[2*j],   bb[2*j]);
        float o1 = fmaf(ds, a[2*j+1], bb[2*j+1]);
        if (RELU) { o0 = fmaxf(o0, 0.f); o1 = fmaxf(o1, 0.f); }
        p[j] = packh2(o0, o1);
    }
    reinterpret_cast<uint4*>(outp)[(size_t)row * (HID / 8) + c8] =
        make_uint4(p[0], p[1], p[2], p[3]);
}

// ============================================================================
extern "C" void kernel_launch(void* const* d_in, const int* in_sizes, int n_in,
                              void* d_out, int out_size)
{
    const float* x    = (const float*)d_in[0];
    const float* Wp   = (const float*)d_in[1];
    const float* bp   = (const float*)d_in[2];
    const float* gcnW = (const float*)d_in[3];
    const float* gcnb = (const float*)d_in[4];
    const float* s1W  = (const float*)d_in[5];
    const float* s1b  = (const float*)d_in[6];
    const float* s2W  = (const float*)d_in[7];
    const float* s2b  = (const float*)d_in[8];
    const float* s3W  = (const float*)d_in[9];
    const float* s3b  = (const float*)d_in[10];
    float* out = (float*)d_out;

    __half *xh, *a0h, *a1h, *suph, *wpT, *gwT, *s1T, *s2T;
    cudaGetSymbolAddress((void**)&xh,   g_xh);
    cudaGetSymbolAddress((void**)&a0h,  g_a0h);
    cudaGetSymbolAddress((void**)&a1h,  g_a1h);
    cudaGetSymbolAddress((void**)&suph, g_suph);
    cudaGetSymbolAddress((void**)&wpT,  g_wpT);
    cudaGetSymbolAddress((void**)&gwT,  g_gwT);
    cudaGetSymbolAddress((void**)&s1T,  g_s1T);
    cudaGetSymbolAddress((void**)&s2T,  g_s2T);

    // Opt in to 96 KB dynamic smem for each GEMM instantiation
    cudaFuncSetAttribute(mma_gemm<0,1,1>, cudaFuncAttributeMaxDynamicSharedMemorySize, GEMM_SMEM);
    cudaFuncSetAttribute(mma_gemm<0,0,1>, cudaFuncAttributeMaxDynamicSharedMemorySize, GEMM_SMEM);
    cudaFuncSetAttribute(mma_gemm<1,1,1>, cudaFuncAttributeMaxDynamicSharedMemorySize, GEMM_SMEM);
    cudaFuncSetAttribute(mma_gemm<1,1,2>, cudaFuncAttributeMaxDynamicSharedMemorySize, GEMM_SMEM);

    // --- ALL weight transposes in one launch + x conversion ---
    prep_weights<<<T_END, 256>>>(Wp, gcnW, s1W, s2W, wpT, gwT, s1T, s2T);
    {
        int n4 = MTOT * FIN / 4;
        half_convert<<<(n4+255)/256, 256>>>((const float4*)x, (uint2*)xh, n4);
    }

    const int st_blocks = (MTOT * (HID / 8) + 255) / 256;

    // 1) h0 = x @ Wp + bp  -> a0 (fp16)
    mma_gemm<0,1,1><<<dim3(HID/BN, MTOT/BM), 256, GEMM_SMEM>>>(
        xh, wpT, bp, nullptr, a0h, nullptr, nullptr, MTOT, HID, FIN);

    // 2) 3 GCN layers: sup = h @ W (fp16), then stencil+bias(+relu) -> a0 (fp16)
    for (int i = 0; i < 3; i++) {
        mma_gemm<0,0,1><<<dim3(HID/BN, MTOT/BM), 256, GEMM_SMEM>>>(
            a0h, gwT + (size_t)i*HID*HID, nullptr, nullptr, suph, nullptr, nullptr,
            MTOT, HID, HID);
        if (i < 2)
            stencil_h<true ><<<st_blocks, 256>>>(suph, gcnb + (size_t)i*HID, a0h);
        else
            stencil_h<false><<<st_blocks, 256>>>(suph, gcnb + (size_t)i*HID, a0h);
    }

    // 3) z1 = relu(h @ s1W + s1b) -> a1 (fp16)
    mma_gemm<1,1,1><<<dim3(SC1/BN, MTOT/BM), 256, GEMM_SMEM>>>(
        a0h, s1T, s1b, nullptr, a1h, nullptr, nullptr, MTOT, SC1, HID);

    // 4+5) out = sigmoid(relu(z1 @ s2W + s2b) @ s3W + s3b)  (fused head epilogue)
    mma_gemm<1,1,2><<<dim3(SC2/BN, MTOT/BM), 256, GEMM_SMEM>>>(
        a1h, s2T, s2b, out, nullptr, s3W, s3b, MTOT, SC2, SC1);
}

// round 17
// speedup vs baseline: 6.7207x; 1.0118x over previous
#include <cuda_runtime.h>
#include <cuda_fp16.h>
#include <cstdint>
#include <math.h>

// Problem dims (fixed by the reference)
#define BATCH 8
#define SEQ   2048
#define FIN   1024
#define HID   512
#define SC1   256
#define SC2   128
#define MTOT  (BATCH * SEQ)   // 16384 rows

// ============================================================================
// Scratch (__device__ globals — no allocations allowed)
// ============================================================================
__device__ __half g_xh  [MTOT * FIN];    // x in fp16              (32 MB)
__device__ __half g_a0h [MTOT * HID];    // activation ping        (16 MB)
__device__ __half g_bh  [MTOT * HID];    // activation pong        (16 MB)
__device__ __half g_a1h [MTOT * SC1];    // score-layer1 act fp16
__device__ __half g_suph[MTOT * HID];    // GCN support, boundary rows only
__device__ __half g_wpT[HID * FIN];      // transposed fp16 weights
__device__ __half g_gwT[3 * HID * HID];
__device__ __half g_s1T[SC1 * HID];
__device__ __half g_s2T[SC2 * SC1];

// ============================================================================
// Baseline-PTX primitives (no sm_103a-only features)
// ============================================================================
__device__ __forceinline__ uint32_t smem_u32(const void* p) {
    uint32_t a;
    asm("{ .reg .u64 t; cvta.to.shared.u64 t, %1; cvt.u32.u64 %0, t; }" : "=r"(a) : "l"(p));
    return a;
}
__device__ __forceinline__ void cpasync16(uint32_t dst, const void* src) {
    asm volatile("cp.async.cg.shared.global [%0], [%1], 16;" :: "r"(dst), "l"(src) : "memory");
}
__device__ __forceinline__ void cp_commit() {
    asm volatile("cp.async.commit_group;" ::: "memory");
}
template <int N>
__device__ __forceinline__ void cp_wait() {
    asm volatile("cp.async.wait_group %0;" :: "n"(N) : "memory");
}
__device__ __forceinline__ void ldm_x4(uint32_t* r, uint32_t addr) {
    asm volatile("ldmatrix.sync.aligned.m8n8.x4.shared.b16 {%0,%1,%2,%3}, [%4];"
        : "=r"(r[0]), "=r"(r[1]), "=r"(r[2]), "=r"(r[3]) : "r"(addr));
}
// m16n8k16 fp16 MMA, fp32 accumulate
__device__ __forceinline__ void mma16816(float* c, const uint32_t* a, const uint32_t* b) {
    asm volatile(
        "mma.sync.aligned.m16n8k16.row.col.f32.f16.f16.f32 "
        "{%0,%1,%2,%3}, {%4,%5,%6,%7}, {%8,%9}, {%0,%1,%2,%3};"
        : "+f"(c[0]), "+f"(c[1]), "+f"(c[2]), "+f"(c[3])
        : "r"(a[0]), "r"(a[1]), "r"(a[2]), "r"(a[3]), "r"(b[0]), "r"(b[1]));
}
__device__ __forceinline__ uint32_t packh2(float a, float b) {
    return (uint32_t)__half_as_ushort(__float2half_rn(a))
         | ((uint32_t)__half_as_ushort(__float2half_rn(b)) << 16);
}

#define INV2 0.707106781186547524f   /* 1/sqrt(2) */
#define INV3 0.577350269189625764f   /* 1/sqrt(3) */

// SMEM tile: 128 rows x 64 fp16 (128 B/row = 8 x 16B chunks). XOR swizzle keeps
// cp.async stores and ldmatrix loads bank-conflict-free:
//   offset = r*128 + ((c16 ^ (r & 7)) << 4)
__device__ __forceinline__ uint32_t swz(int r, int c16) {
    return (uint32_t)(r * 128 + (((c16) ^ (r & 7)) << 4));
}

// ============================================================================
// fp16 single-pass GEMM: C[M,N] = A[M,K] @ B[N,K]^T, fp32 accumulate.
// BM=BN=128, BK=64, 256 threads (8 warps, 4x2), warp tile 32x64.
// 3-stage cp.async pipeline; epilogue staged through SMEM.
// OUTMODE 0: fp32 C.           OUTMODE 1: fp16 C (fp16 smem staging).
// OUTMODE 2: fused score head. OUTMODE 3: fused GCN stencil (interior rows ->
//   Ch as fp16 activations; boundary sup rows {0,1,126,127} -> Csup).
// ============================================================================
#define BM 128
#define BN 128
#define BKC 64
#define ABUF 16384             // bytes per fp16 tile (128 rows * 128 B)
#define STAGE (2 * ABUF)       // A + B = 32 KB
#define NSTAGE 3
#define GEMM_SMEM (NSTAGE * STAGE)   // 98304 B (>= epi 128*130*4 = 66560)
#define EPI_STRIDE 130         // fp32 stride (OUTMODE 0/2/3)
#define EPI_STRIDE_H 132       // fp16 stride in halves (OUTMODE 1), 264 B/row

template <int ACT, int HASBIAS, int OUTMODE>
__global__ __launch_bounds__(256, 2)
void mma_gemm(const __half* __restrict__ A, const __half* __restrict__ B,
              const float* __restrict__ bias,
              float* __restrict__ Cf, __half* __restrict__ Ch,
              __half* __restrict__ Csup,
              const float* __restrict__ W3, const float* __restrict__ B3,
              int M, int N, int K)
{
    extern __shared__ char smem[];
    const uint32_t sb = smem_u32(smem);
    const int tid = threadIdx.x;
    const int wid = tid >> 5, lid = tid & 31;
    const int wm = wid & 3, wn = wid >> 2;          // 4 x 2 warp grid
    const int m0 = blockIdx.y * BM, n0 = blockIdx.x * BN;

    // cp.async g2s for one K-chunk (64 halves) into one stage (A tile + B tile)
    auto g2s = [&](int c, int st) {
        const uint32_t base = sb + st * STAGE;
        const __half* srcA = A + (size_t)m0 * K + c * BKC;
        const __half* srcB = B + (size_t)n0 * K + c * BKC;
#pragma unroll
        for (int i = 0; i < 4; i++) {
            const int q = tid + i * 256;              // 0..1023
            const int r = q >> 3, c16 = q & 7;
            const uint32_t so = swz(r, c16);
            cpasync16(base + so,        srcA + (size_t)r * K + c16 * 8);
            cpasync16(base + ABUF + so, srcB + (size_t)r * K + c16 * 8);
        }
    };

    float acc[2][8][4];
#pragma unroll
    for (int i = 0; i < 2; i++)
#pragma unroll
        for (int j = 0; j < 8; j++)
#pragma unroll
            for (int q = 0; q < 4; q++) acc[i][j][q] = 0.0f;

    // ldmatrix lane decomposition
    const int lt = lid >> 3;         // tile index 0..3 within x4
    const int lj = lid & 7;          // row within 8x8 tile

    const int NC = K / BKC;          // >= 2 for all layers
    g2s(0, 0); cp_commit();
    if (NC > 1) g2s(1, 1);
    cp_commit();

    for (int c = 0; c < NC; c++) {
        cp_wait<1>();                 // stage c landed
        __syncthreads();              // all warps see it; prior stage reads done
        if (c + 2 < NC) g2s(c + 2, (c + 2) % NSTAGE);
        cp_commit();                  // always commit to keep group count fixed

        const uint32_t stg = sb + (c % NSTAGE) * STAGE;
        const uint32_t sA = stg, sB = stg + ABUF;

#pragma unroll
        for (int kk = 0; kk < BKC; kk += 16) {
            // A fragments (m16k16): x4 tiles (m0k0, m8k0, m0k8, m8k8)
            uint32_t a[2][4];
#pragma unroll
            for (int mi = 0; mi < 2; mi++) {
                const int rowA = wm * 32 + mi * 16 + lj + ((lt & 1) << 3);
                ldm_x4(a[mi], sA + swz(rowA, (kk >> 3) + (lt >> 1)));
            }
            // B fragments (two n8k16 per x4): tiles (n0k0, n0k8, n8k0, n8k8)
            uint32_t bf[4][4];
#pragma unroll
            for (int nb = 0; nb < 4; nb++) {
                const int rowB = wn * 64 + nb * 16 + lj + ((lt >> 1) << 3);
                ldm_x4(bf[nb], sB + swz(rowB, (kk >> 3) + (lt & 1)));
            }
            // single-pass fp16 MMA
#pragma unroll
            for (int mi = 0; mi < 2; mi++)
#pragma unroll
                for (int nb = 0; nb < 4; nb++) {
                    mma16816(acc[mi][2 * nb],     a[mi], &bf[nb][0]);
                    mma16816(acc[mi][2 * nb + 1], a[mi], &bf[nb][2]);
                }
        }
    }

    // ---------------- Epilogue (staged through SMEM) ------------------------
    __syncthreads();                       // all warps done reading stages

    if (OUTMODE == 1) {
        // Stage as fp16 (bias+relu applied pre-store): half the smem traffic.
        uint32_t* sh = reinterpret_cast<uint32_t*>(smem);
        const int tq = lid >> 2, tr = lid & 3;
#pragma unroll
        for (int ni = 0; ni < 8; ni++) {
            const int col = wn * 64 + ni * 8 + tr * 2;
            float b0 = 0.f, b1 = 0.f;
            if (HASBIAS) { b0 = bias[n0 + col]; b1 = bias[n0 + col + 1]; }
#pragma unroll
            for (int mi = 0; mi < 2; mi++) {
                const int row = wm * 32 + mi * 16 + tq;
                float v0 = acc[mi][ni][0] + b0, v1 = acc[mi][ni][1] + b1;
                float v2 = acc[mi][ni][2] + b0, v3 = acc[mi][ni][3] + b1;
                if (ACT) {
                    v0 = fmaxf(v0, 0.f); v1 = fmaxf(v1, 0.f);
                    v2 = fmaxf(v2, 0.f); v3 = fmaxf(v3, 0.f);
                }
                sh[(row * EPI_STRIDE_H + col) >> 1]       = packh2(v0, v1);
                sh[((row + 8) * EPI_STRIDE_H + col) >> 1] = packh2(v2, v3);
            }
        }
        __syncthreads();
        // Each warp writes 16 rows; lane l handles 4 consecutive halves (8 B).
        const int cl = lid * 2;      // in u32 units (2 halves each)
#pragma unroll
        for (int i = 0; i < 16; i++) {
            const int r = wid * 16 + i;
            const uint32_t* sp = sh + ((r * EPI_STRIDE_H) >> 1) + cl;
            *reinterpret_cast<uint2*>(Ch + (size_t)(m0 + r) * N + n0 + cl * 2) =
                make_uint2(sp[0], sp[1]);
        }
    } else {
        float* sc = reinterpret_cast<float*>(smem);
        {
            const int tq = lid >> 2, tr = lid & 3;
#pragma unroll
            for (int ni = 0; ni < 8; ni++) {
                const int col = wn * 64 + ni * 8 + tr * 2;
#pragma unroll
                for (int mi = 0; mi < 2; mi++) {
                    const int row = wm * 32 + mi * 16 + tq;
                    sc[row * EPI_STRIDE + col]           = acc[mi][ni][0];
                    sc[row * EPI_STRIDE + col + 1]       = acc[mi][ni][1];
                    sc[(row + 8) * EPI_STRIDE + col]     = acc[mi][ni][2];
                    sc[(row + 8) * EPI_STRIDE + col + 1] = acc[mi][ni][3];
                }
            }
        }
        __syncthreads();

        if (OUTMODE == 2) {
            // Fused head: v = relu(z + b2); out[row] = sigmoid(dot(v, W3) + b3)
            const float4 wv = *reinterpret_cast<const float4*>(W3 + lid * 4);
            const float4 bb = *reinterpret_cast<const float4*>(bias + lid * 4);
            const float b3 = B3[0];
#pragma unroll
            for (int i = 0; i < 16; i++) {
                const int r = wid * 16 + i;
                const float* sp = sc + r * EPI_STRIDE + lid * 4;
                const float v0 = fmaxf(sp[0] + bb.x, 0.f);
                const float v1 = fmaxf(sp[1] + bb.y, 0.f);
                const float v2 = fmaxf(sp[2] + bb.z, 0.f);
                const float v3 = fmaxf(sp[3] + bb.w, 0.f);
                float sum = v0 * wv.x + v1 * wv.y + v2 * wv.z + v3 * wv.w;
#pragma unroll
                for (int o = 16; o > 0; o >>= 1)
                    sum += __shfl_xor_sync(0xFFFFFFFFu, sum, o);
                if (lid == 0) Cf[m0 + r] = 1.0f / (1.0f + expf(-(sum + b3)));
            }
        } else if (OUTMODE == 3) {
            // Fused GCN stencil. Interior rows 1..126 have both neighbors in
            // this tile (s in [1,2046] => ds = INV3 always). Boundary rows 0
            // and 127 are patched by fixup_boundary; persist sup rows
            // {0,1,126,127} for it.
            const int cl = lid * 4;
            const float4 bv = *reinterpret_cast<const float4*>(bias + n0 + cl);
#pragma unroll
            for (int i = 0; i < 16; i++) {
                const int r = wid * 16 + i;
                const float* cm = sc + r * EPI_STRIDE + cl;
                if (r <= 1 || r >= BM - 2) {
                    *reinterpret_cast<uint2*>(Csup + (size_t)(m0 + r) * N + n0 + cl) =
                        make_uint2(packh2(cm[0], cm[1]), packh2(cm[2], cm[3]));
                }
                if (r >= 1 && r <= BM - 2) {
                    const int s = (m0 + r) & (SEQ - 1);
                    const float dl = (s == 1)       ? INV2 : INV3;   // dinv[s-1]
                    const float dr = (s == SEQ - 2) ? INV2 : INV3;   // dinv[s+1]
                    const float* cu = sc + (r - 1) * EPI_STRIDE + cl;
                    const float* cd = sc + (r + 1) * EPI_STRIDE + cl;
                    float v0 = fmaf(INV3, fmaf(dl, cu[0], fmaf(INV3, cm[0], dr * cd[0])), bv.x);
                    float v1 = fmaf(INV3, fmaf(dl, cu[1], fmaf(INV3, cm[1], dr * cd[1])), bv.y);
                    float v2 = fmaf(INV3, fmaf(dl, cu[2], fmaf(INV3, cm[2], dr * cd[2])), bv.z);
                    float v3 = fmaf(INV3, fmaf(dl, cu[3], fmaf(INV3, cm[3], dr * cd[3])), bv.w);
                    if (ACT) {
                        v0 = fmaxf(v0, 0.f); v1 = fmaxf(v1, 0.f);
                        v2 = fmaxf(v2, 0.f); v3 = fmaxf(v3, 0.f);
                    }
                    *reinterpret_cast<uint2*>(Ch + (size_t)(m0 + r) * N + n0 + cl) =
                        make_uint2(packh2(v0, v1), packh2(v2, v3));
                }
            }
        } else {
            const int cl = lid * 4;
            float b0 = 0.f, b1 = 0.f, b2 = 0.f, b3 = 0.f;
            if (HASBIAS) {
                const float4 bv = *reinterpret_cast<const float4*>(bias + n0 + cl);
                b0 = bv.x; b1 = bv.y; b2 = bv.z; b3 = bv.w;
            }
#pragma unroll
            for (int i = 0; i < 16; i++) {
                const int r = wid * 16 + i;
                const float* sp = sc + r * EPI_STRIDE + cl;
                float v0 = sp[0] + b0, v1 = sp[1] + b1, v2 = sp[2] + b2, v3 = sp[3] + b3;
                if (ACT) {
                    v0 = fmaxf(v0, 0.f); v1 = fmaxf(v1, 0.f);
                    v2 = fmaxf(v2, 0.f); v3 = fmaxf(v3, 0.f);
                }
                *reinterpret_cast<float4*>(Cf + (size_t)(m0 + r) * N + n0 + cl) =
                    make_float4(v0, v1, v2, v3);
            }
        }
    }
}

// ============================================================================
// Boundary fixup: stencil for tile-edge rows (r % 128 in {0,127}) using the
// persisted sup rows. 256 rows x 512 cols, fp32 math, fp16 out.
// ============================================================================
__device__ __forceinline__ void unpack8(const uint4 u, float* f) {
    const __half2* h = reinterpret_cast<const __half2*>(&u);
#pragma unroll
    for (int j = 0; j < 4; j++) {
        const float2 t = __half22float2(h[j]);
        f[2 * j] = t.x; f[2 * j + 1] = t.y;
    }
}

template <bool RELU>
__global__ void fixup_boundary(const __half* __restrict__ sup,
                               const float* __restrict__ bias,
                               __half* __restrict__ a0)
{
    const int NB = (MTOT / BM) * 2;          // 256 boundary rows
    const int idx = blockIdx.x * blockDim.x + threadIdx.x;
    if (idx >= NB * (HID / 8)) return;
    const int c8 = idx % (HID / 8);
    const int br = idx / (HID / 8);
    const int r  = (br >> 1) * BM + ((br & 1) ? (BM - 1) : 0);
    const int s  = r & (SEQ - 1);
    const float ds = (s == 0 || s == SEQ - 1) ? INV2 : INV3;

    const uint4* base = reinterpret_cast<const uint4*>(sup) + (size_t)r * (HID / 8) + c8;
    float mid[8], nb[8], a[8];
    unpack8(base[0], mid);
#pragma unroll
    for (int j = 0; j < 8; j++) a[j] = ds * mid[j];
    if (s > 0) {
        const float dl = (s - 1 == 0) ? INV2 : INV3;
        unpack8(base[-(HID / 8)], nb);
#pragma unroll
        for (int j = 0; j < 8; j++) a[j] = fmaf(dl, nb[j], a[j]);
    }
    if (s < SEQ - 1) {
        const float dr = (s + 1 == SEQ - 1) ? INV2 : INV3;
        unpack8(base[(HID / 8)], nb);
#pragma unroll
        for (int j = 0; j < 8; j++) a[j] = fmaf(dr, nb[j], a[j]);
    }
    const float4 bv0 = reinterpret_cast<const float4*>(bias)[c8 * 2];
    const float4 bv1 = reinterpret_cast<const float4*>(bias)[c8 * 2 + 1];
    const float bb[8] = {bv0.x, bv0.y, bv0.z, bv0.w, bv1.x, bv1.y, bv1.z, bv1.w};
    uint32_t p[4];
#pragma unroll
    for (int j = 0; j < 4; j++) {
        float o0 = fmaf(ds, a[2*j],   bb[2*j]);
        float o1 = fmaf(ds, a[2*j+1], bb[2*j+1]);
        if (RELU) { o0 = fmaxf(o0, 0.f); o1 = fmaxf(o1, 0.f); }
        p[j] = packh2(o0, o1);
    }
    reinterpret_cast<uint4*>(a0)[(size_t)r * (HID / 8) + c8] =
        make_uint4(p[0], p[1], p[2], p[3]);
}

// ============================================================================
// Batched weight prep: ALL 6 transposes in ONE launch (block-range job table).
// ============================================================================
#define T_GW0   512          // Wp: (1024/32)*(512/32) = 512 tiles
#define T_GW1   768          // each gcn: 16*16 = 256
#define T_GW2   1024
#define T_S1    1280
#define T_S2    1408         // s1: 16*8 = 128
#define T_END   1440         // s2: 8*4 = 32

__global__ __launch_bounds__(256)
void prep_weights(const float* __restrict__ Wp, const float* __restrict__ gcnW,
                  const float* __restrict__ s1W, const float* __restrict__ s2W,
                  __half* __restrict__ wpT, __half* __restrict__ gwT,
                  __half* __restrict__ s1T, __half* __restrict__ s2T)
{
    __shared__ float tile[32][33];
    const int b = blockIdx.x;
    const float* W; __half* WT; int K, N, lt;
    if (b < T_GW0)      { W = Wp;  WT = wpT; K = FIN; N = HID; lt = b; }
    else if (b < T_GW1) { W = gcnW;                 WT = gwT;                 K = HID; N = HID; lt = b - T_GW0; }
    else if (b < T_GW2) { W = gcnW + HID*HID;       WT = gwT + HID*HID;       K = HID; N = HID; lt = b - T_GW1; }
    else if (b < T_S1)  { W = gcnW + 2*HID*HID;     WT = gwT + 2*HID*HID;     K = HID; N = HID; lt = b - T_GW2; }
    else if (b < T_S2)  { W = s1W; WT = s1T; K = HID; N = SC1; lt = b - T_S1; }
    else                { W = s2W; WT = s2T; K = SC1; N = SC2; lt = b - T_S2; }
    const int kt = K / 32;
    const int k0 = (lt % kt) * 32, n0 = (lt / kt) * 32;
    {
        const int c = threadIdx.x & 31, r8 = threadIdx.x >> 5;
#pragma unroll
        for (int r = r8; r < 32; r += 8)
            tile[r][c] = W[(size_t)(k0 + r) * N + n0 + c];
    }
    __syncthreads();
    const int nloc = threadIdx.x >> 3;       // 0..31
    const int kq   = threadIdx.x & 7;        // 4 k's each
    const uint32_t p0 = packh2(tile[kq*4+0][nloc], tile[kq*4+1][nloc]);
    const uint32_t p1 = packh2(tile[kq*4+2][nloc], tile[kq*4+3][nloc]);
    *reinterpret_cast<uint2*>(WT + (size_t)(n0 + nloc) * K + k0 + kq * 4) =
        make_uint2(p0, p1);
}

// x: fp32 -> fp16 (big, bandwidth-bound, stays separate)
__global__ void half_convert(const float4* __restrict__ in,
                             uint2* __restrict__ outp, int n4)
{
    const int i = blockIdx.x * blockDim.x + threadIdx.x;
    if (i >= n4) return;
    const float4 v = in[i];
    outp[i] = make_uint2(packh2(v.x, v.y), packh2(v.z, v.w));
}

// ============================================================================
extern "C" void kernel_launch(void* const* d_in, const int* in_sizes, int n_in,
                              void* d_out, int out_size)
{
    const float* x    = (const float*)d_in[0];
    const float* Wp   = (const float*)d_in[1];
    const float* bp   = (const float*)d_in[2];
    const float* gcnW = (const float*)d_in[3];
    const float* gcnb = (const float*)d_in[4];
    const float* s1W  = (const float*)d_in[5];
    const float* s1b  = (const float*)d_in[6];
    const float* s2W  = (const float*)d_in[7];
    const float* s2b  = (const float*)d_in[8];
    const float* s3W  = (const float*)d_in[9];
    const float* s3b  = (const float*)d_in[10];
    float* out = (float*)d_out;

    __half *xh, *a0h, *bh, *a1h, *suph, *wpT, *gwT, *s1T, *s2T;
    cudaGetSymbolAddress((void**)&xh,   g_xh);
    cudaGetSymbolAddress((void**)&a0h,  g_a0h);
    cudaGetSymbolAddress((void**)&bh,   g_bh);
    cudaGetSymbolAddress((void**)&a1h,  g_a1h);
    cudaGetSymbolAddress((void**)&suph, g_suph);
    cudaGetSymbolAddress((void**)&wpT,  g_wpT);
    cudaGetSymbolAddress((void**)&gwT,  g_gwT);
    cudaGetSymbolAddress((void**)&s1T,  g_s1T);
    cudaGetSymbolAddress((void**)&s2T,  g_s2T);

    // Opt in to 96 KB dynamic smem for each GEMM instantiation
    cudaFuncSetAttribute(mma_gemm<0,1,1>, cudaFuncAttributeMaxDynamicSharedMemorySize, GEMM_SMEM);
    cudaFuncSetAttribute(mma_gemm<1,0,3>, cudaFuncAttributeMaxDynamicSharedMemorySize, GEMM_SMEM);
    cudaFuncSetAttribute(mma_gemm<0,0,3>, cudaFuncAttributeMaxDynamicSharedMemorySize, GEMM_SMEM);
    cudaFuncSetAttribute(mma_gemm<1,1,1>, cudaFuncAttributeMaxDynamicSharedMemorySize, GEMM_SMEM);
    cudaFuncSetAttribute(mma_gemm<1,1,2>, cudaFuncAttributeMaxDynamicSharedMemorySize, GEMM_SMEM);

    // --- ALL weight transposes in one launch + x conversion ---
    prep_weights<<<T_END, 256>>>(Wp, gcnW, s1W, s2W, wpT, gwT, s1T, s2T);
    {
        int n4 = MTOT * FIN / 4;
        half_convert<<<(n4+255)/256, 256>>>((const float4*)x, (uint2*)xh, n4);
    }

    const dim3 gdim(HID/BN, MTOT/BM);
    const int fix_blocks = ((MTOT / BM) * 2 * (HID / 8) + 255) / 256;   // 64

    // 1) h0 = x @ Wp + bp  -> a0 (fp16)
    mma_gemm<0,1,1><<<gdim, 256, GEMM_SMEM>>>(
        xh, wpT, bp, nullptr, a0h, nullptr, nullptr, nullptr, MTOT, HID, FIN);

    // 2) GCN layers with fused stencil epilogue + boundary fixup.
    //    Ping-pong activations (output buffer != input buffer).
    // GCN0: a0h -> bh   (relu)
    mma_gemm<1,0,3><<<gdim, 256, GEMM_SMEM>>>(
        a0h, gwT, gcnb, nullptr, bh, suph, nullptr, nullptr, MTOT, HID, HID);
    fixup_boundary<true><<<fix_blocks, 256>>>(suph, gcnb, bh);
    // GCN1: bh -> a0h   (relu)
    mma_gemm<1,0,3><<<gdim, 256, GEMM_SMEM>>>(
        bh, gwT + (size_t)HID*HID, gcnb + HID, nullptr, a0h, suph,
        nullptr, nullptr, MTOT, HID, HID);
    fixup_boundary<true><<<fix_blocks, 256>>>(suph, gcnb + HID, a0h);
    // GCN2: a0h -> bh   (no relu)
    mma_gemm<0,0,3><<<gdim, 256, GEMM_SMEM>>>(
        a0h, gwT + (size_t)2*HID*HID, gcnb + 2*HID, nullptr, bh, suph,
        nullptr, nullptr, MTOT, HID, HID);
    fixup_boundary<false><<<fix_blocks, 256>>>(suph, gcnb + 2*HID, bh);

    // 3) z1 = relu(h @ s1W + s1b) -> a1 (fp16)
    mma_gemm<1,1,1><<<dim3(SC1/BN, MTOT/BM), 256, GEMM_SMEM>>>(
        bh, s1T, s1b, nullptr, a1h, nullptr, nullptr, nullptr, MTOT, SC1, HID);

    // 4+5) out = sigmoid(relu(z1 @ s2W + s2b) @ s3W + s3b)  (fused head epilogue)
    mma_gemm<1,1,2><<<dim3(SC2/BN, MTOT/BM), 256, GEMM_SMEM>>>(
        a1h, s2T, s2b, out, nullptr, nullptr, s3W, s3b, MTOT, SC2, SC1);
}